// round 1
// baseline (speedup 1.0000x reference)
#include <cuda_runtime.h>
#include <cuda_bf16.h>

// Problem dims (fixed per reference)
#define B_  2
#define T_  2048
#define C_  1024
#define H_  16
#define HD_ 64
#define C3_ 3072
#define M_ROWS (B_ * T_)   // 4096

// Scratch (allocation-free rule: device globals)
__device__ float g_qkv[B_ * T_ * C3_];   // [4096, 3072]
__device__ float g_att[B_ * T_ * C_];    // [4096, 1024]

// ---------------------------------------------------------------------------
// SGEMM: C[M,N] = A[M,K] @ B[K,N], row-major, fp32
// 128x128 tile, BK=8, 256 threads, 8x8 per thread
// ---------------------------------------------------------------------------
#define BM 128
#define BN 128
#define BK 8

__global__ __launch_bounds__(256) void sgemm_kernel(
    const float* __restrict__ A, const float* __restrict__ Bm,
    float* __restrict__ Cm, int M, int N, int K)
{
    __shared__ float As[BK][BM];
    __shared__ float Bs[BK][BN];

    const int tid = threadIdx.x;
    const int bx = blockIdx.x;   // N tile
    const int by = blockIdx.y;   // M tile

    const float* Ablk = A + (size_t)by * BM * K;
    const float* Bblk = Bm + (size_t)bx * BN;

    const int arow = tid >> 1;          // 0..127
    const int acol = (tid & 1) * 4;     // 0 or 4
    const int brow = tid >> 5;          // 0..7
    const int bcol = (tid & 31) * 4;    // 0..124

    const int ty = tid >> 4;            // 0..15
    const int tx = tid & 15;            // 0..15

    float acc[8][8];
#pragma unroll
    for (int i = 0; i < 8; i++)
#pragma unroll
        for (int j = 0; j < 8; j++) acc[i][j] = 0.f;

    for (int k0 = 0; k0 < K; k0 += BK) {
        float4 av = *(const float4*)(Ablk + (size_t)arow * K + k0 + acol);
        As[acol + 0][arow] = av.x;
        As[acol + 1][arow] = av.y;
        As[acol + 2][arow] = av.z;
        As[acol + 3][arow] = av.w;
        float4 bv = *(const float4*)(Bblk + (size_t)(k0 + brow) * N + bcol);
        *(float4*)&Bs[brow][bcol] = bv;
        __syncthreads();

#pragma unroll
        for (int k = 0; k < BK; k++) {
            float ar[8], br[8];
            *(float4*)&ar[0] = *(const float4*)&As[k][ty * 8];
            *(float4*)&ar[4] = *(const float4*)&As[k][ty * 8 + 4];
            *(float4*)&br[0] = *(const float4*)&Bs[k][tx * 8];
            *(float4*)&br[4] = *(const float4*)&Bs[k][tx * 8 + 4];
#pragma unroll
            for (int i = 0; i < 8; i++)
#pragma unroll
                for (int j = 0; j < 8; j++)
                    acc[i][j] = fmaf(ar[i], br[j], acc[i][j]);
        }
        __syncthreads();
    }

#pragma unroll
    for (int i = 0; i < 8; i++) {
        size_t row = (size_t)by * BM + ty * 8 + i;
        float* crow = Cm + row * N + (size_t)bx * BN + tx * 8;
        *(float4*)&crow[0] = *(float4*)&acc[i][0];
        *(float4*)&crow[4] = *(float4*)&acc[i][4];
    }
}

// ---------------------------------------------------------------------------
// Flash attention fp32, causal + column-0 emphasis.
// Grid: (T/64, B*H). Block: 256 threads. Tiles 64x64, hd=64.
// Smem: Qts[d][r], Kts[d][c], Vs[c][d], Ss[r][c], all ld=68 (pad).
// ---------------------------------------------------------------------------
#define LDP 68
#define NEG_BIG (-1e30f)

__global__ __launch_bounds__(256) void attn_kernel(
    const float* __restrict__ qkv, float* __restrict__ out)
{
    extern __shared__ float sm[];
    float* Qts  = sm;                    // [64][LDP] : Qts[d*LDP + r]
    float* Kts  = Qts + 64 * LDP;        // [64][LDP] : Kts[d*LDP + c]
    float* Vs   = Kts + 64 * LDP;        // [64][LDP] : Vs[c*LDP + d]
    float* Ss   = Vs  + 64 * LDP;        // [64][LDP] : Ss[r*LDP + c]
    float* mrow = Ss  + 64 * LDP;        // [64]
    float* lrow = mrow + 64;             // [64]
    float* arow = lrow + 64;             // [64]

    const int tid = threadIdx.x;
    const int qt  = blockIdx.x;
    const int bh  = blockIdx.y;
    const int b   = bh >> 4;
    const int h   = bh & 15;
    const int q0  = qt * 64;
    const float scale = 0.125f;   // 1/sqrt(64)

    const int ty = tid >> 4;     // 0..15 -> rows ty*4..+3
    const int tx = tid & 15;     // 0..15 -> cols tx*4..+3

    // Load Q tile transposed into Qts[d][r]
    {
        const int lrw = tid >> 4;          // 0..15
        const int d4  = (tid & 15) * 4;    // 0..60
#pragma unroll
        for (int rr = 0; rr < 4; rr++) {
            int row = lrw + rr * 16;
            float4 v = *(const float4*)(qkv + (size_t)(b * T_ + q0 + row) * C3_ + h * HD_ + d4);
            Qts[(d4 + 0) * LDP + row] = v.x;
            Qts[(d4 + 1) * LDP + row] = v.y;
            Qts[(d4 + 2) * LDP + row] = v.z;
            Qts[(d4 + 3) * LDP + row] = v.w;
        }
    }
    if (tid < 64) { mrow[tid] = NEG_BIG; lrow[tid] = 0.f; }

    float acc[4][4];
#pragma unroll
    for (int i = 0; i < 4; i++)
#pragma unroll
        for (int j = 0; j < 4; j++) acc[i][j] = 0.f;

    for (int kt = 0; kt <= qt; kt++) {
        const int k0 = kt * 64;
        __syncthreads();  // protect Kts/Vs/Ss reuse (and Q/m/l init on iter 0)

        // Load K (transposed) and V tiles
        {
            const int lrw = tid >> 4;
            const int d4  = (tid & 15) * 4;
#pragma unroll
            for (int rr = 0; rr < 4; rr++) {
                int row = lrw + rr * 16;
                size_t base = (size_t)(b * T_ + k0 + row) * C3_ + h * HD_;
                float4 kv = *(const float4*)(qkv + base + C_ + d4);
                Kts[(d4 + 0) * LDP + row] = kv.x;
                Kts[(d4 + 1) * LDP + row] = kv.y;
                Kts[(d4 + 2) * LDP + row] = kv.z;
                Kts[(d4 + 3) * LDP + row] = kv.w;
                float4 vv = *(const float4*)(qkv + base + 2 * C_ + d4);
                *(float4*)&Vs[row * LDP + d4] = vv;
            }
        }
        __syncthreads();

        // S = Q @ K^T  (4x4 per thread)
        float s[4][4];
#pragma unroll
        for (int i = 0; i < 4; i++)
#pragma unroll
            for (int j = 0; j < 4; j++) s[i][j] = 0.f;

#pragma unroll 8
        for (int d = 0; d < 64; d++) {
            float a[4], bb[4];
            a[0] = Qts[d * LDP + ty * 4 + 0];
            a[1] = Qts[d * LDP + ty * 4 + 1];
            a[2] = Qts[d * LDP + ty * 4 + 2];
            a[3] = Qts[d * LDP + ty * 4 + 3];
            *(float4*)&bb[0] = *(const float4*)&Kts[d * LDP + tx * 4];
#pragma unroll
            for (int i = 0; i < 4; i++)
#pragma unroll
                for (int j = 0; j < 4; j++)
                    s[i][j] = fmaf(a[i], bb[j], s[i][j]);
        }

        // scale + emphasis + causal mask, store to Ss
#pragma unroll
        for (int i = 0; i < 4; i++) {
            int gr = q0 + ty * 4 + i;
#pragma unroll
            for (int j = 0; j < 4; j++) {
                int gc = k0 + tx * 4 + j;
                float v = s[i][j] * scale;
                if (gc == 0) v += 1.0f;          // EMPHASIS
                if (gc > gr) v = NEG_BIG;        // causal
                Ss[(ty * 4 + i) * LDP + tx * 4 + j] = v;
            }
        }
        __syncthreads();

        // Online softmax per row (threads 0..63)
        if (tid < 64) {
            const int r = tid;
            float mold = mrow[r];
            float mx = mold;
#pragma unroll 8
            for (int c = 0; c < 64; c++) mx = fmaxf(mx, Ss[r * LDP + c]);
            float sum = 0.f;
#pragma unroll 8
            for (int c = 0; c < 64; c++) {
                float p = __expf(Ss[r * LDP + c] - mx);
                Ss[r * LDP + c] = p;
                sum += p;
            }
            float alpha = __expf(mold - mx);
            mrow[r] = mx;
            lrow[r] = lrow[r] * alpha + sum;
            arow[r] = alpha;
        }
        __syncthreads();

        // Rescale acc and accumulate P @ V
        float al[4];
        al[0] = arow[ty * 4 + 0];
        al[1] = arow[ty * 4 + 1];
        al[2] = arow[ty * 4 + 2];
        al[3] = arow[ty * 4 + 3];
#pragma unroll
        for (int i = 0; i < 4; i++)
#pragma unroll
            for (int j = 0; j < 4; j++) acc[i][j] *= al[i];

#pragma unroll 8
        for (int c = 0; c < 64; c++) {
            float a[4], bb[4];
            a[0] = Ss[(ty * 4 + 0) * LDP + c];
            a[1] = Ss[(ty * 4 + 1) * LDP + c];
            a[2] = Ss[(ty * 4 + 2) * LDP + c];
            a[3] = Ss[(ty * 4 + 3) * LDP + c];
            *(float4*)&bb[0] = *(const float4*)&Vs[c * LDP + tx * 4];
#pragma unroll
            for (int i = 0; i < 4; i++)
#pragma unroll
                for (int j = 0; j < 4; j++)
                    acc[i][j] = fmaf(a[i], bb[j], acc[i][j]);
        }
    }

    // Epilogue: normalize and write out[b, q0+r, h*64 + d]
    float linv[4];
    linv[0] = 1.f / lrow[ty * 4 + 0];
    linv[1] = 1.f / lrow[ty * 4 + 1];
    linv[2] = 1.f / lrow[ty * 4 + 2];
    linv[3] = 1.f / lrow[ty * 4 + 3];
#pragma unroll
    for (int i = 0; i < 4; i++) {
        size_t row = (size_t)(b * T_ + q0 + ty * 4 + i);
        float* orow = out + row * C_ + h * HD_ + tx * 4;
#pragma unroll
        for (int j = 0; j < 4; j++) orow[j] = acc[i][j] * linv[i];
    }
}

// ---------------------------------------------------------------------------
extern "C" void kernel_launch(void* const* d_in, const int* in_sizes, int n_in,
                              void* d_out, int out_size)
{
    const float* x  = (const float*)d_in[0];
    const float* Wa = (const float*)d_in[1];
    const float* Wp = (const float*)d_in[2];
    float* y = (float*)d_out;

    float* qkv = nullptr;
    float* att = nullptr;
    cudaGetSymbolAddress((void**)&qkv, g_qkv);
    cudaGetSymbolAddress((void**)&att, g_att);

    // 1) qkv = x @ W_attn   [4096,1024] @ [1024,3072]
    {
        dim3 grid(C3_ / BN, M_ROWS / BM);
        sgemm_kernel<<<grid, 256>>>(x, Wa, qkv, M_ROWS, C3_, C_);
    }

    // 2) flash attention
    {
        int smem = (4 * 64 * LDP + 3 * 64) * (int)sizeof(float);
        cudaFuncSetAttribute(attn_kernel, cudaFuncAttributeMaxDynamicSharedMemorySize, smem);
        dim3 grid(T_ / 64, B_ * H_);
        attn_kernel<<<grid, 256, smem>>>(qkv, att);
    }

    // 3) y = att @ W_proj   [4096,1024] @ [1024,1024]
    {
        dim3 grid(C_ / BN, M_ROWS / BM);
        sgemm_kernel<<<grid, 256>>>(att, Wp, y, M_ROWS, C_, C_);
    }
}

// round 3
// speedup vs baseline: 1.3952x; 1.3952x over previous
#include <cuda_runtime.h>
#include <cuda_bf16.h>
#include <cstdint>

// Problem dims (fixed per reference)
#define B_  2
#define T_  2048
#define C_  1024
#define H_  16
#define HD_ 64
#define C3_ 3072
#define M_ROWS (B_ * T_)   // 4096

// ---------------------------------------------------------------------------
// Scratch (allocation-free rule: device globals)
// ---------------------------------------------------------------------------
__device__ float g_qkv[M_ROWS * C3_];          // 48MB
__device__ float g_att[M_ROWS * C_];           // 16MB
__device__ __nv_bfloat16 g_xh[M_ROWS * C_];
__device__ __nv_bfloat16 g_xl[M_ROWS * C_];
__device__ __nv_bfloat16 g_wah[C3_ * C_];      // W_attn^T split [N=3072, K=1024]
__device__ __nv_bfloat16 g_wal[C3_ * C_];
__device__ __nv_bfloat16 g_wph[C_ * C_];       // W_proj^T split [N=1024, K=1024]
__device__ __nv_bfloat16 g_wpl[C_ * C_];
__device__ __nv_bfloat16 g_ah[M_ROWS * C_];
__device__ __nv_bfloat16 g_al[M_ROWS * C_];

// ---------------------------------------------------------------------------
__device__ __forceinline__ uint32_t smem_u32(const void* p) {
    uint32_t a;
    asm("{ .reg .u64 t; cvta.to.shared.u64 t, %1; cvt.u32.u64 %0, t; }" : "=r"(a) : "l"(p));
    return a;
}
__device__ __forceinline__ void cp_async16(uint32_t saddr, const void* gaddr) {
    asm volatile("cp.async.cg.shared.global [%0], [%1], 16;" :: "r"(saddr), "l"(gaddr));
}
__device__ __forceinline__ void cp_commit() {
    asm volatile("cp.async.commit_group;" ::: "memory");
}
template <int N>
__device__ __forceinline__ void cp_wait() {
    asm volatile("cp.async.wait_group %0;" :: "n"(N) : "memory");
}
__device__ __forceinline__ void ldm_x4(uint32_t& r0, uint32_t& r1, uint32_t& r2, uint32_t& r3,
                                       uint32_t addr) {
    asm volatile("ldmatrix.sync.aligned.m8n8.x4.shared.b16 {%0,%1,%2,%3}, [%4];"
                 : "=r"(r0), "=r"(r1), "=r"(r2), "=r"(r3) : "r"(addr));
}
__device__ __forceinline__ void mma_bf16(float* c, uint32_t a0, uint32_t a1, uint32_t a2,
                                         uint32_t a3, uint32_t b0, uint32_t b1) {
    asm volatile(
        "mma.sync.aligned.m16n8k16.row.col.f32.bf16.bf16.f32 "
        "{%0,%1,%2,%3}, {%4,%5,%6,%7}, {%8,%9}, {%0,%1,%2,%3};"
        : "+f"(c[0]), "+f"(c[1]), "+f"(c[2]), "+f"(c[3])
        : "r"(a0), "r"(a1), "r"(a2), "r"(a3), "r"(b0), "r"(b1));
}

// ---------------------------------------------------------------------------
// Split fp32 -> (hi, lo) bf16
// ---------------------------------------------------------------------------
__global__ __launch_bounds__(256) void split_kernel(
    const float* __restrict__ in, __nv_bfloat16* __restrict__ hi,
    __nv_bfloat16* __restrict__ lo, int n4)
{
    int i = blockIdx.x * blockDim.x + threadIdx.x;
    if (i >= n4) return;
    float4 v = ((const float4*)in)[i];
    __nv_bfloat16 h0 = __float2bfloat16(v.x), h1 = __float2bfloat16(v.y);
    __nv_bfloat16 h2 = __float2bfloat16(v.z), h3 = __float2bfloat16(v.w);
    __nv_bfloat16 l0 = __float2bfloat16(v.x - __bfloat162float(h0));
    __nv_bfloat16 l1 = __float2bfloat16(v.y - __bfloat162float(h1));
    __nv_bfloat16 l2 = __float2bfloat16(v.z - __bfloat162float(h2));
    __nv_bfloat16 l3 = __float2bfloat16(v.w - __bfloat162float(h3));
    __nv_bfloat162* ph = (__nv_bfloat162*)hi + i * 2;
    __nv_bfloat162* pl = (__nv_bfloat162*)lo + i * 2;
    ph[0] = __nv_bfloat162{h0, h1}; ph[1] = __nv_bfloat162{h2, h3};
    pl[0] = __nv_bfloat162{l0, l1}; pl[1] = __nv_bfloat162{l2, l3};
}

// Split + transpose: in [K,N] fp32 -> hiT/loT [N,K] bf16
__global__ __launch_bounds__(256) void split_transpose_kernel(
    const float* __restrict__ in, __nv_bfloat16* __restrict__ hiT,
    __nv_bfloat16* __restrict__ loT, int K, int N)
{
    __shared__ float t[32][33];
    int n0 = blockIdx.x * 32, k0 = blockIdx.y * 32;
    int tx = threadIdx.x, ty = threadIdx.y;   // 32 x 8
#pragma unroll
    for (int i = 0; i < 32; i += 8)
        t[ty + i][tx] = in[(size_t)(k0 + ty + i) * N + n0 + tx];
    __syncthreads();
#pragma unroll
    for (int i = 0; i < 32; i += 8) {
        float v = t[tx][ty + i];
        __nv_bfloat16 h = __float2bfloat16(v);
        __nv_bfloat16 l = __float2bfloat16(v - __bfloat162float(h));
        size_t o = (size_t)(n0 + ty + i) * K + k0 + tx;
        hiT[o] = h; loT[o] = l;
    }
}

// ---------------------------------------------------------------------------
// bf16x3 GEMM via mma.sync:  C[M,N] = A[M,K] @ Bt[N,K]^T  (fp32 out)
// 128x128 tile, BK=32, 256 threads (8 warps, 4x2), double-buffered cp.async.
// smem tiles padded to stride 40 elems for conflict-free ldmatrix.
// ---------------------------------------------------------------------------
#define GBM 128
#define GBN 128
#define GBK 32
#define LDT 40                          // padded stride (elements)
#define TILE_B (128 * LDT * 2)          // 10240 bytes per tile
#define STAGE_B (4 * TILE_B)            // Ah, Al, Bh, Bl
#define SMEM_GEMM (2 * STAGE_B)         // 81920 bytes

__global__ __launch_bounds__(256, 1) void gemm_bf16x3_kernel(
    const __nv_bfloat16* __restrict__ Ah, const __nv_bfloat16* __restrict__ Al,
    const __nv_bfloat16* __restrict__ Bh, const __nv_bfloat16* __restrict__ Bl,
    float* __restrict__ Cm, int M, int N, int K)
{
    extern __shared__ char smem[];
    const uint32_t sb = smem_u32(smem);
    const int tid = threadIdx.x;
    const int wid = tid >> 5, lane = tid & 31;
    const int warp_m = wid >> 1;        // 0..3  -> 32 rows
    const int warp_n = wid & 1;         // 0..1  -> 64 cols
    const int m0 = blockIdx.y * GBM;
    const int n0 = blockIdx.x * GBN;

    const __nv_bfloat16* gsrc[4] = {Ah, Al, Bh, Bl};
    const int gbase[4] = {m0, m0, n0, n0};

    float acc[2][8][4];
#pragma unroll
    for (int i = 0; i < 2; i++)
#pragma unroll
        for (int j = 0; j < 8; j++)
#pragma unroll
            for (int q = 0; q < 4; q++) acc[i][j][q] = 0.f;

    // --- async tile loader: stage s, k-chunk ch ---
    auto load_stage = [&](int s, int ch) {
        const size_t koff = (size_t)ch * GBK;
        uint32_t sbase = sb + s * STAGE_B;
#pragma unroll
        for (int t4 = 0; t4 < 4; t4++) {
            const __nv_bfloat16* src = gsrc[t4];
            uint32_t tb = sbase + t4 * TILE_B;
#pragma unroll
            for (int i = 0; i < 2; i++) {
                int chunk = tid + i * 256;          // 0..511
                int row = chunk >> 2, seg = chunk & 3;
                cp_async16(tb + (uint32_t)(row * LDT + seg * 8) * 2,
                           src + (size_t)(gbase[t4] + row) * K + koff + seg * 8);
            }
        }
    };

    // ldmatrix lane address offsets (elements)
    const int lrow = lane & 15;
    const int lcol = (lane >> 4) << 3;

    auto compute_stage = [&](int s) {
        uint32_t sbase = sb + s * STAGE_B;
        uint32_t sAh = sbase;
        uint32_t sAl = sbase + TILE_B;
        uint32_t sBh = sbase + 2 * TILE_B;
        uint32_t sBl = sbase + 3 * TILE_B;
#pragma unroll
        for (int ks = 0; ks < 2; ks++) {
            const int k0 = ks * 16;
            // A fragments: hi & lo, 2 m-tiles each
            uint32_t ah[2][4], al[2][4];
#pragma unroll
            for (int mi = 0; mi < 2; mi++) {
                int r = warp_m * 32 + mi * 16 + lrow;
                uint32_t off = (uint32_t)(r * LDT + k0 + lcol) * 2;
                ldm_x4(ah[mi][0], ah[mi][1], ah[mi][2], ah[mi][3], sAh + off);
                ldm_x4(al[mi][0], al[mi][1], al[mi][2], al[mi][3], sAl + off);
            }
            // B fragments: hi & lo, 8 n8-tiles (4 ldmatrix.x4 each)
            uint32_t bh[8][2], bl[8][2];
#pragma unroll
            for (int nt = 0; nt < 4; nt++) {
                int r = warp_n * 64 + nt * 16 + lrow;
                uint32_t off = (uint32_t)(r * LDT + k0 + lcol) * 2;
                uint32_t r0, r1, r2, r3;
                ldm_x4(r0, r1, r2, r3, sBh + off);
                bh[nt * 2][0] = r0; bh[nt * 2 + 1][0] = r1;
                bh[nt * 2][1] = r2; bh[nt * 2 + 1][1] = r3;
                ldm_x4(r0, r1, r2, r3, sBl + off);
                bl[nt * 2][0] = r0; bl[nt * 2 + 1][0] = r1;
                bl[nt * 2][1] = r2; bl[nt * 2 + 1][1] = r3;
            }
#pragma unroll
            for (int mi = 0; mi < 2; mi++)
#pragma unroll
                for (int ni = 0; ni < 8; ni++) {
                    mma_bf16(acc[mi][ni], ah[mi][0], ah[mi][1], ah[mi][2], ah[mi][3],
                             bh[ni][0], bh[ni][1]);
                    mma_bf16(acc[mi][ni], ah[mi][0], ah[mi][1], ah[mi][2], ah[mi][3],
                             bl[ni][0], bl[ni][1]);
                    mma_bf16(acc[mi][ni], al[mi][0], al[mi][1], al[mi][2], al[mi][3],
                             bh[ni][0], bh[ni][1]);
                }
        }
    };

    const int nch = K / GBK;
    load_stage(0, 0);
    cp_commit();
    for (int ch = 0; ch < nch; ch++) {
        if (ch + 1 < nch) {
            load_stage((ch + 1) & 1, ch + 1);
            cp_commit();
            cp_wait<1>();
        } else {
            cp_wait<0>();
        }
        __syncthreads();
        compute_stage(ch & 1);
        __syncthreads();
    }

    // Epilogue: direct stores (float2 per frag half)
    const int gid = lane >> 2;          // 0..7
    const int tig = lane & 3;           // 0..3
#pragma unroll
    for (int mi = 0; mi < 2; mi++) {
        int rbase = m0 + warp_m * 32 + mi * 16 + gid;
#pragma unroll
        for (int ni = 0; ni < 8; ni++) {
            int col = n0 + warp_n * 64 + ni * 8 + tig * 2;
            float* p0 = Cm + (size_t)rbase * N + col;
            float* p1 = Cm + (size_t)(rbase + 8) * N + col;
            p0[0] = acc[mi][ni][0]; p0[1] = acc[mi][ni][1];
            p1[0] = acc[mi][ni][2]; p1[1] = acc[mi][ni][3];
        }
    }
}

// ---------------------------------------------------------------------------
// Flash attention fp32, causal + column-0 emphasis (parallel softmax)
// ---------------------------------------------------------------------------
#define LDP 68
#define NEG_BIG (-1e30f)

__global__ __launch_bounds__(256) void attn_kernel(
    const float* __restrict__ qkv, float* __restrict__ out)
{
    extern __shared__ float sm[];
    float* Qts  = sm;                    // [64][LDP] : Qts[d*LDP + r]
    float* Kts  = Qts + 64 * LDP;
    float* Vs   = Kts + 64 * LDP;
    float* Ss   = Vs  + 64 * LDP;
    float* mrow = Ss  + 64 * LDP;
    float* lrow = mrow + 64;
    float* arow = lrow + 64;

    const int tid = threadIdx.x;
    const int qt  = blockIdx.x;
    const int bh  = blockIdx.y;
    const int b   = bh >> 4;
    const int h   = bh & 15;
    const int q0  = qt * 64;
    const float scale = 0.125f;

    const int ty = tid >> 4;
    const int tx = tid & 15;

    {
        const int lrw = tid >> 4;
        const int d4  = (tid & 15) * 4;
#pragma unroll
        for (int rr = 0; rr < 4; rr++) {
            int row = lrw + rr * 16;
            float4 v = *(const float4*)(qkv + (size_t)(b * T_ + q0 + row) * C3_ + h * HD_ + d4);
            Qts[(d4 + 0) * LDP + row] = v.x;
            Qts[(d4 + 1) * LDP + row] = v.y;
            Qts[(d4 + 2) * LDP + row] = v.z;
            Qts[(d4 + 3) * LDP + row] = v.w;
        }
    }
    if (tid < 64) { mrow[tid] = NEG_BIG; lrow[tid] = 0.f; }

    float acc[4][4];
#pragma unroll
    for (int i = 0; i < 4; i++)
#pragma unroll
        for (int j = 0; j < 4; j++) acc[i][j] = 0.f;

    for (int kt = 0; kt <= qt; kt++) {
        const int k0 = kt * 64;
        __syncthreads();

        {
            const int lrw = tid >> 4;
            const int d4  = (tid & 15) * 4;
#pragma unroll
            for (int rr = 0; rr < 4; rr++) {
                int row = lrw + rr * 16;
                size_t base = (size_t)(b * T_ + k0 + row) * C3_ + h * HD_;
                float4 kv = *(const float4*)(qkv + base + C_ + d4);
                Kts[(d4 + 0) * LDP + row] = kv.x;
                Kts[(d4 + 1) * LDP + row] = kv.y;
                Kts[(d4 + 2) * LDP + row] = kv.z;
                Kts[(d4 + 3) * LDP + row] = kv.w;
                float4 vv = *(const float4*)(qkv + base + 2 * C_ + d4);
                *(float4*)&Vs[row * LDP + d4] = vv;
            }
        }
        __syncthreads();

        float s[4][4];
#pragma unroll
        for (int i = 0; i < 4; i++)
#pragma unroll
            for (int j = 0; j < 4; j++) s[i][j] = 0.f;

#pragma unroll 8
        for (int d = 0; d < 64; d++) {
            float a[4], bb[4];
            a[0] = Qts[d * LDP + ty * 4 + 0];
            a[1] = Qts[d * LDP + ty * 4 + 1];
            a[2] = Qts[d * LDP + ty * 4 + 2];
            a[3] = Qts[d * LDP + ty * 4 + 3];
            *(float4*)&bb[0] = *(const float4*)&Kts[d * LDP + tx * 4];
#pragma unroll
            for (int i = 0; i < 4; i++)
#pragma unroll
                for (int j = 0; j < 4; j++)
                    s[i][j] = fmaf(a[i], bb[j], s[i][j]);
        }

#pragma unroll
        for (int i = 0; i < 4; i++) {
            int gr = q0 + ty * 4 + i;
#pragma unroll
            for (int j = 0; j < 4; j++) {
                int gc = k0 + tx * 4 + j;
                float v = s[i][j] * scale;
                if (gc == 0) v += 1.0f;
                if (gc > gr) v = NEG_BIG;
                Ss[(ty * 4 + i) * LDP + tx * 4 + j] = v;
            }
        }
        __syncthreads();

        {
            const int r  = tid >> 2;
            const int qs = tid & 3;
            float vals[16];
#pragma unroll
            for (int u = 0; u < 4; u++)
                *(float4*)&vals[u * 4] = *(const float4*)&Ss[r * LDP + qs * 16 + u * 4];
            float mx = vals[0];
#pragma unroll
            for (int u = 1; u < 16; u++) mx = fmaxf(mx, vals[u]);
            mx = fmaxf(mx, __shfl_xor_sync(0xffffffffu, mx, 1));
            mx = fmaxf(mx, __shfl_xor_sync(0xffffffffu, mx, 2));
            float mold = mrow[r];
            float mnew = fmaxf(mold, mx);
            float sum = 0.f;
#pragma unroll
            for (int u = 0; u < 16; u++) {
                float p = __expf(vals[u] - mnew);
                vals[u] = p;
                sum += p;
            }
#pragma unroll
            for (int u = 0; u < 4; u++)
                *(float4*)&Ss[r * LDP + qs * 16 + u * 4] = *(float4*)&vals[u * 4];
            sum += __shfl_xor_sync(0xffffffffu, sum, 1);
            sum += __shfl_xor_sync(0xffffffffu, sum, 2);
            if (qs == 0) {
                float al = __expf(mold - mnew);
                mrow[r] = mnew;
                lrow[r] = lrow[r] * al + sum;
                arow[r] = al;
            }
        }
        __syncthreads();

        float al4[4];
        al4[0] = arow[ty * 4 + 0];
        al4[1] = arow[ty * 4 + 1];
        al4[2] = arow[ty * 4 + 2];
        al4[3] = arow[ty * 4 + 3];
#pragma unroll
        for (int i = 0; i < 4; i++)
#pragma unroll
            for (int j = 0; j < 4; j++) acc[i][j] *= al4[i];

#pragma unroll 8
        for (int c = 0; c < 64; c++) {
            float a[4], bb[4];
            a[0] = Ss[(ty * 4 + 0) * LDP + c];
            a[1] = Ss[(ty * 4 + 1) * LDP + c];
            a[2] = Ss[(ty * 4 + 2) * LDP + c];
            a[3] = Ss[(ty * 4 + 3) * LDP + c];
            *(float4*)&bb[0] = *(const float4*)&Vs[c * LDP + tx * 4];
#pragma unroll
            for (int i = 0; i < 4; i++)
#pragma unroll
                for (int j = 0; j < 4; j++)
                    acc[i][j] = fmaf(a[i], bb[j], acc[i][j]);
        }
    }

    float linv[4];
    linv[0] = 1.f / lrow[ty * 4 + 0];
    linv[1] = 1.f / lrow[ty * 4 + 1];
    linv[2] = 1.f / lrow[ty * 4 + 2];
    linv[3] = 1.f / lrow[ty * 4 + 3];
#pragma unroll
    for (int i = 0; i < 4; i++) {
        size_t row = (size_t)(b * T_ + q0 + ty * 4 + i);
        float* orow = out + row * C_ + h * HD_ + tx * 4;
#pragma unroll
        for (int j = 0; j < 4; j++) orow[j] = acc[i][j] * linv[i];
    }
}

// ---------------------------------------------------------------------------
extern "C" void kernel_launch(void* const* d_in, const int* in_sizes, int n_in,
                              void* d_out, int out_size)
{
    const float* x  = (const float*)d_in[0];
    const float* Wa = (const float*)d_in[1];
    const float* Wp = (const float*)d_in[2];
    float* y = (float*)d_out;

    float *qkv, *att;
    __nv_bfloat16 *xh, *xl, *wah, *wal, *wph, *wpl, *ah, *al;
    cudaGetSymbolAddress((void**)&qkv, g_qkv);
    cudaGetSymbolAddress((void**)&att, g_att);
    cudaGetSymbolAddress((void**)&xh, g_xh);
    cudaGetSymbolAddress((void**)&xl, g_xl);
    cudaGetSymbolAddress((void**)&wah, g_wah);
    cudaGetSymbolAddress((void**)&wal, g_wal);
    cudaGetSymbolAddress((void**)&wph, g_wph);
    cudaGetSymbolAddress((void**)&wpl, g_wpl);
    cudaGetSymbolAddress((void**)&ah, g_ah);
    cudaGetSymbolAddress((void**)&al, g_al);

    int attn_smem = (4 * 64 * LDP + 3 * 64) * (int)sizeof(float);
    cudaFuncSetAttribute(gemm_bf16x3_kernel,
                         cudaFuncAttributeMaxDynamicSharedMemorySize, SMEM_GEMM);
    cudaFuncSetAttribute(attn_kernel,
                         cudaFuncAttributeMaxDynamicSharedMemorySize, attn_smem);

    // 1) splits
    {
        int n4 = M_ROWS * C_ / 4;
        split_kernel<<<(n4 + 255) / 256, 256>>>(x, xh, xl, n4);
        dim3 grid_a(C3_ / 32, C_ / 32);
        split_transpose_kernel<<<grid_a, dim3(32, 8)>>>(Wa, wah, wal, C_, C3_);
        dim3 grid_p(C_ / 32, C_ / 32);
        split_transpose_kernel<<<grid_p, dim3(32, 8)>>>(Wp, wph, wpl, C_, C_);
    }

    // 2) qkv = x @ W_attn  (bf16x3 mma.sync)
    {
        dim3 grid(C3_ / GBN, M_ROWS / GBM);
        gemm_bf16x3_kernel<<<grid, 256, SMEM_GEMM>>>(xh, xl, wah, wal, qkv, M_ROWS, C3_, C_);
    }

    // 3) flash attention (fp32)
    {
        dim3 grid(T_ / 64, B_ * H_);
        attn_kernel<<<grid, 256, attn_smem>>>(qkv, att);
    }

    // 4) split attention output
    {
        int n4 = M_ROWS * C_ / 4;
        split_kernel<<<(n4 + 255) / 256, 256>>>(att, ah, al, n4);
    }

    // 5) y = att @ W_proj  (bf16x3 mma.sync)
    {
        dim3 grid(C_ / GBN, M_ROWS / GBM);
        gemm_bf16x3_kernel<<<grid, 256, SMEM_GEMM>>>(ah, al, wph, wpl, y, M_ROWS, C_, C_);
    }
}

// round 5
// speedup vs baseline: 2.3885x; 1.7119x over previous
#include <cuda_runtime.h>
#include <cuda_bf16.h>
#include <cstdint>

// Problem dims (fixed per reference)
#define B_  2
#define T_  2048
#define C_  1024
#define H_  16
#define HD_ 64
#define C3_ 3072
#define M_ROWS (B_ * T_)   // 4096

// ---------------------------------------------------------------------------
// Scratch (allocation-free rule: device globals)
// ---------------------------------------------------------------------------
__device__ __nv_bfloat16 g_qkvh[M_ROWS * C3_];   // qkv hi  [4096, 3072]
__device__ __nv_bfloat16 g_qkvl[M_ROWS * C3_];   // qkv lo
__device__ __nv_bfloat16 g_xh[M_ROWS * C_];
__device__ __nv_bfloat16 g_xl[M_ROWS * C_];
__device__ __nv_bfloat16 g_wah[C3_ * C_];        // W_attn^T split [N=3072, K=1024]
__device__ __nv_bfloat16 g_wal[C3_ * C_];
__device__ __nv_bfloat16 g_wph[C_ * C_];         // W_proj^T split [N=1024, K=1024]
__device__ __nv_bfloat16 g_wpl[C_ * C_];
__device__ __nv_bfloat16 g_ah[M_ROWS * C_];      // attention out hi
__device__ __nv_bfloat16 g_al[M_ROWS * C_];      // attention out lo

// ---------------------------------------------------------------------------
__device__ __forceinline__ uint32_t smem_u32(const void* p) {
    uint32_t a;
    asm("{ .reg .u64 t; cvta.to.shared.u64 t, %1; cvt.u32.u64 %0, t; }" : "=r"(a) : "l"(p));
    return a;
}
__device__ __forceinline__ void cp_async16(uint32_t saddr, const void* gaddr) {
    asm volatile("cp.async.cg.shared.global [%0], [%1], 16;" :: "r"(saddr), "l"(gaddr));
}
__device__ __forceinline__ void cp_commit() {
    asm volatile("cp.async.commit_group;" ::: "memory");
}
template <int N>
__device__ __forceinline__ void cp_wait() {
    asm volatile("cp.async.wait_group %0;" :: "n"(N) : "memory");
}
__device__ __forceinline__ void ldm_x4(uint32_t& r0, uint32_t& r1, uint32_t& r2, uint32_t& r3,
                                       uint32_t addr) {
    asm volatile("ldmatrix.sync.aligned.m8n8.x4.shared.b16 {%0,%1,%2,%3}, [%4];"
                 : "=r"(r0), "=r"(r1), "=r"(r2), "=r"(r3) : "r"(addr));
}
__device__ __forceinline__ void ldm_x4_t(uint32_t& r0, uint32_t& r1, uint32_t& r2, uint32_t& r3,
                                         uint32_t addr) {
    asm volatile("ldmatrix.sync.aligned.m8n8.x4.trans.shared.b16 {%0,%1,%2,%3}, [%4];"
                 : "=r"(r0), "=r"(r1), "=r"(r2), "=r"(r3) : "r"(addr));
}
__device__ __forceinline__ void mma_bf16(float* c, uint32_t a0, uint32_t a1, uint32_t a2,
                                         uint32_t a3, uint32_t b0, uint32_t b1) {
    asm volatile(
        "mma.sync.aligned.m16n8k16.row.col.f32.bf16.bf16.f32 "
        "{%0,%1,%2,%3}, {%4,%5,%6,%7}, {%8,%9}, {%0,%1,%2,%3};"
        : "+f"(c[0]), "+f"(c[1]), "+f"(c[2]), "+f"(c[3])
        : "r"(a0), "r"(a1), "r"(a2), "r"(a3), "r"(b0), "r"(b1));
}
__device__ __forceinline__ uint32_t pack_bf16(float lo_elem, float hi_elem) {
    __nv_bfloat162 t = __floats2bfloat162_rn(lo_elem, hi_elem);
    return *(uint32_t*)&t;
}
__device__ __forceinline__ float bf16_residual(float v) {
    return v - __bfloat162float(__float2bfloat16(v));
}

// ---------------------------------------------------------------------------
// Split fp32 -> (hi, lo) bf16
// ---------------------------------------------------------------------------
__global__ __launch_bounds__(256) void split_kernel(
    const float* __restrict__ in, __nv_bfloat16* __restrict__ hi,
    __nv_bfloat16* __restrict__ lo, int n4)
{
    int i = blockIdx.x * blockDim.x + threadIdx.x;
    if (i >= n4) return;
    float4 v = ((const float4*)in)[i];
    __nv_bfloat16 h0 = __float2bfloat16(v.x), h1 = __float2bfloat16(v.y);
    __nv_bfloat16 h2 = __float2bfloat16(v.z), h3 = __float2bfloat16(v.w);
    __nv_bfloat16 l0 = __float2bfloat16(v.x - __bfloat162float(h0));
    __nv_bfloat16 l1 = __float2bfloat16(v.y - __bfloat162float(h1));
    __nv_bfloat16 l2 = __float2bfloat16(v.z - __bfloat162float(h2));
    __nv_bfloat16 l3 = __float2bfloat16(v.w - __bfloat162float(h3));
    __nv_bfloat162* ph = (__nv_bfloat162*)hi + i * 2;
    __nv_bfloat162* pl = (__nv_bfloat162*)lo + i * 2;
    ph[0] = __nv_bfloat162{h0, h1}; ph[1] = __nv_bfloat162{h2, h3};
    pl[0] = __nv_bfloat162{l0, l1}; pl[1] = __nv_bfloat162{l2, l3};
}

// Split + transpose: in [K,N] fp32 -> hiT/loT [N,K] bf16
__global__ __launch_bounds__(256) void split_transpose_kernel(
    const float* __restrict__ in, __nv_bfloat16* __restrict__ hiT,
    __nv_bfloat16* __restrict__ loT, int K, int N)
{
    __shared__ float t[32][33];
    int n0 = blockIdx.x * 32, k0 = blockIdx.y * 32;
    int tx = threadIdx.x, ty = threadIdx.y;   // 32 x 8
#pragma unroll
    for (int i = 0; i < 32; i += 8)
        t[ty + i][tx] = in[(size_t)(k0 + ty + i) * N + n0 + tx];
    __syncthreads();
#pragma unroll
    for (int i = 0; i < 32; i += 8) {
        float v = t[tx][ty + i];
        __nv_bfloat16 h = __float2bfloat16(v);
        __nv_bfloat16 l = __float2bfloat16(v - __bfloat162float(h));
        size_t o = (size_t)(n0 + ty + i) * K + k0 + tx;
        hiT[o] = h; loT[o] = l;
    }
}

// ---------------------------------------------------------------------------
// bf16x3 GEMM via mma.sync:  C[M,N] = A[M,K] @ Bt[N,K]^T
// 128x128 tile, BK=32, 256 threads, double-buffered cp.async.
// SPLIT=false: fp32 out to Cm.  SPLIT=true: bf16 hi/lo out to Ch/Cl.
// ---------------------------------------------------------------------------
#define GBM 128
#define GBN 128
#define GBK 32
#define LDT 40
#define TILE_B (128 * LDT * 2)
#define STAGE_B (4 * TILE_B)
#define SMEM_GEMM (2 * STAGE_B)

template <bool SPLIT>
__global__ __launch_bounds__(256, 1) void gemm_bf16x3_kernel(
    const __nv_bfloat16* __restrict__ Ah, const __nv_bfloat16* __restrict__ Al,
    const __nv_bfloat16* __restrict__ Bh, const __nv_bfloat16* __restrict__ Bl,
    float* __restrict__ Cm, __nv_bfloat16* __restrict__ Ch,
    __nv_bfloat16* __restrict__ Cl, int M, int N, int K)
{
    extern __shared__ char smem[];
    const uint32_t sb = smem_u32(smem);
    const int tid = threadIdx.x;
    const int wid = tid >> 5, lane = tid & 31;
    const int warp_m = wid >> 1;
    const int warp_n = wid & 1;
    const int m0 = blockIdx.y * GBM;
    const int n0 = blockIdx.x * GBN;

    const __nv_bfloat16* gsrc[4] = {Ah, Al, Bh, Bl};
    const int gbase[4] = {m0, m0, n0, n0};

    float acc[2][8][4];
#pragma unroll
    for (int i = 0; i < 2; i++)
#pragma unroll
        for (int j = 0; j < 8; j++)
#pragma unroll
            for (int q = 0; q < 4; q++) acc[i][j][q] = 0.f;

    auto load_stage = [&](int s, int ch) {
        const size_t koff = (size_t)ch * GBK;
        uint32_t sbase = sb + s * STAGE_B;
#pragma unroll
        for (int t4 = 0; t4 < 4; t4++) {
            const __nv_bfloat16* src = gsrc[t4];
            uint32_t tb = sbase + t4 * TILE_B;
#pragma unroll
            for (int i = 0; i < 2; i++) {
                int chunk = tid + i * 256;
                int row = chunk >> 2, seg = chunk & 3;
                cp_async16(tb + (uint32_t)(row * LDT + seg * 8) * 2,
                           src + (size_t)(gbase[t4] + row) * K + koff + seg * 8);
            }
        }
    };

    const int lrow = lane & 15;
    const int lcol = (lane >> 4) << 3;

    auto compute_stage = [&](int s) {
        uint32_t sbase = sb + s * STAGE_B;
        uint32_t sAh = sbase, sAl = sbase + TILE_B;
        uint32_t sBh = sbase + 2 * TILE_B, sBl = sbase + 3 * TILE_B;
#pragma unroll
        for (int ks = 0; ks < 2; ks++) {
            const int k0 = ks * 16;
            uint32_t ahf[2][4], alf[2][4];
#pragma unroll
            for (int mi = 0; mi < 2; mi++) {
                int r = warp_m * 32 + mi * 16 + lrow;
                uint32_t off = (uint32_t)(r * LDT + k0 + lcol) * 2;
                ldm_x4(ahf[mi][0], ahf[mi][1], ahf[mi][2], ahf[mi][3], sAh + off);
                ldm_x4(alf[mi][0], alf[mi][1], alf[mi][2], alf[mi][3], sAl + off);
            }
            uint32_t bhf[8][2], blf[8][2];
#pragma unroll
            for (int nt = 0; nt < 4; nt++) {
                int r = warp_n * 64 + nt * 16 + lrow;
                uint32_t off = (uint32_t)(r * LDT + k0 + lcol) * 2;
                uint32_t r0, r1, r2, r3;
                ldm_x4(r0, r1, r2, r3, sBh + off);
                bhf[nt * 2][0] = r0; bhf[nt * 2 + 1][0] = r1;
                bhf[nt * 2][1] = r2; bhf[nt * 2 + 1][1] = r3;
                ldm_x4(r0, r1, r2, r3, sBl + off);
                blf[nt * 2][0] = r0; blf[nt * 2 + 1][0] = r1;
                blf[nt * 2][1] = r2; blf[nt * 2 + 1][1] = r3;
            }
#pragma unroll
            for (int mi = 0; mi < 2; mi++)
#pragma unroll
                for (int ni = 0; ni < 8; ni++) {
                    mma_bf16(acc[mi][ni], ahf[mi][0], ahf[mi][1], ahf[mi][2], ahf[mi][3],
                             bhf[ni][0], bhf[ni][1]);
                    mma_bf16(acc[mi][ni], ahf[mi][0], ahf[mi][1], ahf[mi][2], ahf[mi][3],
                             blf[ni][0], blf[ni][1]);
                    mma_bf16(acc[mi][ni], alf[mi][0], alf[mi][1], alf[mi][2], alf[mi][3],
                             bhf[ni][0], bhf[ni][1]);
                }
        }
    };

    const int nch = K / GBK;
    load_stage(0, 0);
    cp_commit();
    for (int ch = 0; ch < nch; ch++) {
        if (ch + 1 < nch) {
            load_stage((ch + 1) & 1, ch + 1);
            cp_commit();
            cp_wait<1>();
        } else {
            cp_wait<0>();
        }
        __syncthreads();
        compute_stage(ch & 1);
        __syncthreads();
    }

    const int gid = lane >> 2;
    const int tig = lane & 3;
#pragma unroll
    for (int mi = 0; mi < 2; mi++) {
        int rbase = m0 + warp_m * 32 + mi * 16 + gid;
#pragma unroll
        for (int ni = 0; ni < 8; ni++) {
            int col = n0 + warp_n * 64 + ni * 8 + tig * 2;
            if (SPLIT) {
                float v0 = acc[mi][ni][0], v1 = acc[mi][ni][1];
                float v2 = acc[mi][ni][2], v3 = acc[mi][ni][3];
                *(uint32_t*)(Ch + (size_t)rbase * N + col) = pack_bf16(v0, v1);
                *(uint32_t*)(Cl + (size_t)rbase * N + col) =
                    pack_bf16(bf16_residual(v0), bf16_residual(v1));
                *(uint32_t*)(Ch + (size_t)(rbase + 8) * N + col) = pack_bf16(v2, v3);
                *(uint32_t*)(Cl + (size_t)(rbase + 8) * N + col) =
                    pack_bf16(bf16_residual(v2), bf16_residual(v3));
            } else {
                float* p0 = Cm + (size_t)rbase * N + col;
                float* p1 = Cm + (size_t)(rbase + 8) * N + col;
                p0[0] = acc[mi][ni][0]; p0[1] = acc[mi][ni][1];
                p1[0] = acc[mi][ni][2]; p1[1] = acc[mi][ni][3];
            }
        }
    }
}

// ---------------------------------------------------------------------------
// Tensor-core flash attention (bf16x3), causal + column-0 emphasis.
// Grid (T/128, B*H), 256 threads. 128 q-rows per CTA, 64 k-cols per iter.
// ---------------------------------------------------------------------------
#define AT_LD 72
#define AT_QT_B (128 * AT_LD * 2)          // 18432 per q tile (hi or lo)
#define AT_KV_T (64 * AT_LD * 2)           // 9216 per kv tile
#define AT_STG  (4 * AT_KV_T)              // Kh,Kl,Vh,Vl
#define SMEM_ATTN (2 * AT_QT_B + 2 * AT_STG)   // 110592

__global__ __launch_bounds__(256, 1) void attn_mma_kernel(
    const __nv_bfloat16* __restrict__ qkvh, const __nv_bfloat16* __restrict__ qkvl,
    __nv_bfloat16* __restrict__ ah, __nv_bfloat16* __restrict__ al)
{
    extern __shared__ char smem[];
    const uint32_t sb = smem_u32(smem);
    const int tid = threadIdx.x;
    const int wid = tid >> 5, lane = tid & 31;
    const int qt = blockIdx.x;
    const int bh = blockIdx.y;
    const int b = bh >> 4, h = bh & 15;
    const int q0 = qt * 128;

    const uint32_t sQh = sb, sQl = sb + AT_QT_B;
    const uint32_t stg0 = sb + 2 * AT_QT_B;

    // --- load Q (hi/lo) ---
#pragma unroll
    for (int i = 0; i < 8; i++) {
        int chunk = tid + i * 256;      // 0..2047
        int isLo = chunk >> 10;
        int c2 = chunk & 1023;
        int row = c2 >> 3, seg = c2 & 7;
        const __nv_bfloat16* src = (isLo ? qkvl : qkvh) +
            (size_t)(b * T_ + q0 + row) * C3_ + h * HD_ + seg * 8;
        cp_async16((isLo ? sQl : sQh) + (uint32_t)(row * AT_LD + seg * 8) * 2, src);
    }
    cp_commit();

    auto load_kv = [&](int s, int it) {
        const int k0 = it * 64;
        uint32_t sbase = stg0 + s * AT_STG;
#pragma unroll
        for (int i = 0; i < 8; i++) {
            int chunk = tid + i * 256;      // 0..2047
            int t4 = chunk >> 9;            // 0=Kh 1=Kl 2=Vh 3=Vl
            int c2 = chunk & 511;
            int row = c2 >> 3, seg = c2 & 7;
            const __nv_bfloat16* base = (t4 & 1) ? qkvl : qkvh;
            size_t coloff = (t4 < 2) ? (size_t)(C_ + h * HD_) : (size_t)(2 * C_ + h * HD_);
            cp_async16(sbase + t4 * AT_KV_T + (uint32_t)(row * AT_LD + seg * 8) * 2,
                       base + (size_t)(b * T_ + k0 + row) * C3_ + coloff + seg * 8);
        }
    };
    load_kv(0, 0);
    cp_commit();
    cp_wait<0>();
    __syncthreads();

    const int lrow = lane & 15;
    const int lcol = (lane >> 4) << 3;
    const int gid = lane >> 2;
    const int tig = lane & 3;

    // --- Q fragments (persistent) ---
    uint32_t qh[4][4], ql[4][4];
#pragma unroll
    for (int kt = 0; kt < 4; kt++) {
        uint32_t off = (uint32_t)((wid * 16 + lrow) * AT_LD + kt * 16 + lcol) * 2;
        ldm_x4(qh[kt][0], qh[kt][1], qh[kt][2], qh[kt][3], sQh + off);
        ldm_x4(ql[kt][0], ql[kt][1], ql[kt][2], ql[kt][3], sQl + off);
    }

    float o[8][4];
#pragma unroll
    for (int i = 0; i < 8; i++)
#pragma unroll
        for (int j = 0; j < 4; j++) o[i][j] = 0.f;
    float m0r = -1e30f, m1r = -1e30f, l0r = 0.f, l1r = 0.f;

    const int niters = 2 * qt + 2;
    for (int it = 0; it < niters; it++) {
        if (it + 1 < niters) {
            load_kv((it + 1) & 1, it + 1);
            cp_commit();
            cp_wait<1>();
        } else {
            cp_wait<0>();
        }
        __syncthreads();

        const uint32_t s_ = stg0 + (it & 1) * AT_STG;
        const uint32_t sKh = s_, sKl = s_ + AT_KV_T;
        const uint32_t sVh = s_ + 2 * AT_KV_T, sVl = s_ + 3 * AT_KV_T;
        const int k0 = it * 64;
        const bool active = (q0 + wid * 16 + 15 >= k0);

        if (active) {
            // ---- S = Q @ K^T (3-term) ----
            float s[8][4];
#pragma unroll
            for (int i = 0; i < 8; i++)
#pragma unroll
                for (int j = 0; j < 4; j++) s[i][j] = 0.f;

#pragma unroll
            for (int kt = 0; kt < 4; kt++) {
#pragma unroll
                for (int np = 0; np < 4; np++) {
                    uint32_t boff = (uint32_t)((np * 16 + lrow) * AT_LD + kt * 16 + lcol) * 2;
                    uint32_t h0, h1, h2, h3, e0, e1, e2, e3;
                    ldm_x4(h0, h1, h2, h3, sKh + boff);
                    ldm_x4(e0, e1, e2, e3, sKl + boff);
                    mma_bf16(s[np * 2],     qh[kt][0], qh[kt][1], qh[kt][2], qh[kt][3], h0, h2);
                    mma_bf16(s[np * 2 + 1], qh[kt][0], qh[kt][1], qh[kt][2], qh[kt][3], h1, h3);
                    mma_bf16(s[np * 2],     qh[kt][0], qh[kt][1], qh[kt][2], qh[kt][3], e0, e2);
                    mma_bf16(s[np * 2 + 1], qh[kt][0], qh[kt][1], qh[kt][2], qh[kt][3], e1, e3);
                    mma_bf16(s[np * 2],     ql[kt][0], ql[kt][1], ql[kt][2], ql[kt][3], h0, h2);
                    mma_bf16(s[np * 2 + 1], ql[kt][0], ql[kt][1], ql[kt][2], ql[kt][3], h1, h3);
                }
            }

            // ---- scale + emphasis + causal mask ----
#pragma unroll
            for (int ni = 0; ni < 8; ni++)
#pragma unroll
                for (int e = 0; e < 4; e++) s[ni][e] *= 0.125f;
            if (it == 0 && tig == 0) { s[0][0] += 1.0f; s[0][2] += 1.0f; }
            const int grow0 = q0 + wid * 16 + gid;
            const int grow1 = grow0 + 8;
            if (k0 + 63 > q0 + wid * 16) {
#pragma unroll
                for (int ni = 0; ni < 8; ni++) {
                    int gc = k0 + ni * 8 + tig * 2;
                    if (gc > grow0)     s[ni][0] = -1e30f;
                    if (gc + 1 > grow0) s[ni][1] = -1e30f;
                    if (gc > grow1)     s[ni][2] = -1e30f;
                    if (gc + 1 > grow1) s[ni][3] = -1e30f;
                }
            }

            // ---- online softmax (rows grow0, grow1) ----
            float mx0 = s[0][0], mx1 = s[0][2];
#pragma unroll
            for (int ni = 0; ni < 8; ni++) {
                mx0 = fmaxf(mx0, fmaxf(s[ni][0], s[ni][1]));
                mx1 = fmaxf(mx1, fmaxf(s[ni][2], s[ni][3]));
            }
            mx0 = fmaxf(mx0, __shfl_xor_sync(0xffffffffu, mx0, 1));
            mx0 = fmaxf(mx0, __shfl_xor_sync(0xffffffffu, mx0, 2));
            mx1 = fmaxf(mx1, __shfl_xor_sync(0xffffffffu, mx1, 1));
            mx1 = fmaxf(mx1, __shfl_xor_sync(0xffffffffu, mx1, 2));
            float mn0 = fmaxf(m0r, mx0), mn1 = fmaxf(m1r, mx1);
            float a0 = __expf(m0r - mn0), a1 = __expf(m1r - mn1);
            m0r = mn0; m1r = mn1;
            float sum0 = 0.f, sum1 = 0.f;
#pragma unroll
            for (int ni = 0; ni < 8; ni++) {
                s[ni][0] = __expf(s[ni][0] - mn0);
                s[ni][1] = __expf(s[ni][1] - mn0);
                s[ni][2] = __expf(s[ni][2] - mn1);
                s[ni][3] = __expf(s[ni][3] - mn1);
                sum0 += s[ni][0] + s[ni][1];
                sum1 += s[ni][2] + s[ni][3];
            }
            sum0 += __shfl_xor_sync(0xffffffffu, sum0, 1);
            sum0 += __shfl_xor_sync(0xffffffffu, sum0, 2);
            sum1 += __shfl_xor_sync(0xffffffffu, sum1, 1);
            sum1 += __shfl_xor_sync(0xffffffffu, sum1, 2);
            l0r = l0r * a0 + sum0;
            l1r = l1r * a1 + sum1;

            // ---- rescale O ----
#pragma unroll
            for (int ni = 0; ni < 8; ni++) {
                o[ni][0] *= a0; o[ni][1] *= a0;
                o[ni][2] *= a1; o[ni][3] *= a1;
            }

            // ---- PV (3-term): P hi/lo from s, V via ldmatrix.trans ----
#pragma unroll
            for (int kt = 0; kt < 4; kt++) {
                uint32_t ph[4], pl[4];
                {
                    float v0 = s[2 * kt][0], v1 = s[2 * kt][1];
                    float v2 = s[2 * kt][2], v3 = s[2 * kt][3];
                    float w0 = s[2 * kt + 1][0], w1 = s[2 * kt + 1][1];
                    float w2 = s[2 * kt + 1][2], w3 = s[2 * kt + 1][3];
                    ph[0] = pack_bf16(v0, v1); ph[1] = pack_bf16(v2, v3);
                    ph[2] = pack_bf16(w0, w1); ph[3] = pack_bf16(w2, w3);
                    pl[0] = pack_bf16(bf16_residual(v0), bf16_residual(v1));
                    pl[1] = pack_bf16(bf16_residual(v2), bf16_residual(v3));
                    pl[2] = pack_bf16(bf16_residual(w0), bf16_residual(w1));
                    pl[3] = pack_bf16(bf16_residual(w2), bf16_residual(w3));
                }
#pragma unroll
                for (int dp = 0; dp < 4; dp++) {
                    uint32_t voff = (uint32_t)((kt * 16 + lrow) * AT_LD + dp * 16 + lcol) * 2;
                    uint32_t h0, h1, h2, h3, e0, e1, e2, e3;
                    ldm_x4_t(h0, h1, h2, h3, sVh + voff);
                    ldm_x4_t(e0, e1, e2, e3, sVl + voff);
                    mma_bf16(o[dp * 2],     ph[0], ph[1], ph[2], ph[3], h0, h1);
                    mma_bf16(o[dp * 2 + 1], ph[0], ph[1], ph[2], ph[3], h2, h3);
                    mma_bf16(o[dp * 2],     ph[0], ph[1], ph[2], ph[3], e0, e1);
                    mma_bf16(o[dp * 2 + 1], ph[0], ph[1], ph[2], ph[3], e2, e3);
                    mma_bf16(o[dp * 2],     pl[0], pl[1], pl[2], pl[3], h0, h1);
                    mma_bf16(o[dp * 2 + 1], pl[0], pl[1], pl[2], pl[3], h2, h3);
                }
            }
        }
    }

    // ---- epilogue: normalize, split hi/lo, store ----
    const float inv0 = 1.f / l0r, inv1 = 1.f / l1r;
    const int grow0 = q0 + wid * 16 + gid;
    const size_t r0o = (size_t)(b * T_ + grow0) * C_;
    const size_t r1o = (size_t)(b * T_ + grow0 + 8) * C_;
#pragma unroll
    for (int ni = 0; ni < 8; ni++) {
        int col = h * HD_ + ni * 8 + tig * 2;
        float v0 = o[ni][0] * inv0, v1 = o[ni][1] * inv0;
        float v2 = o[ni][2] * inv1, v3 = o[ni][3] * inv1;
        *(uint32_t*)(ah + r0o + col) = pack_bf16(v0, v1);
        *(uint32_t*)(al + r0o + col) = pack_bf16(bf16_residual(v0), bf16_residual(v1));
        *(uint32_t*)(ah + r1o + col) = pack_bf16(v2, v3);
        *(uint32_t*)(al + r1o + col) = pack_bf16(bf16_residual(v2), bf16_residual(v3));
    }
}

// ---------------------------------------------------------------------------
extern "C" void kernel_launch(void* const* d_in, const int* in_sizes, int n_in,
                              void* d_out, int out_size)
{
    const float* x  = (const float*)d_in[0];
    const float* Wa = (const float*)d_in[1];
    const float* Wp = (const float*)d_in[2];
    float* y = (float*)d_out;

    __nv_bfloat16 *qkvh, *qkvl, *xh, *xl, *wah, *wal, *wph, *wpl, *ah, *al;
    cudaGetSymbolAddress((void**)&qkvh, g_qkvh);
    cudaGetSymbolAddress((void**)&qkvl, g_qkvl);
    cudaGetSymbolAddress((void**)&xh, g_xh);
    cudaGetSymbolAddress((void**)&xl, g_xl);
    cudaGetSymbolAddress((void**)&wah, g_wah);
    cudaGetSymbolAddress((void**)&wal, g_wal);
    cudaGetSymbolAddress((void**)&wph, g_wph);
    cudaGetSymbolAddress((void**)&wpl, g_wpl);
    cudaGetSymbolAddress((void**)&ah, g_ah);
    cudaGetSymbolAddress((void**)&al, g_al);

    cudaFuncSetAttribute(gemm_bf16x3_kernel<true>,
                         cudaFuncAttributeMaxDynamicSharedMemorySize, SMEM_GEMM);
    cudaFuncSetAttribute(gemm_bf16x3_kernel<false>,
                         cudaFuncAttributeMaxDynamicSharedMemorySize, SMEM_GEMM);
    cudaFuncSetAttribute(attn_mma_kernel,
                         cudaFuncAttributeMaxDynamicSharedMemorySize, SMEM_ATTN);

    // 1) splits
    {
        int n4 = M_ROWS * C_ / 4;
        split_kernel<<<(n4 + 255) / 256, 256>>>(x, xh, xl, n4);
        dim3 grid_a(C3_ / 32, C_ / 32);
        split_transpose_kernel<<<grid_a, dim3(32, 8)>>>(Wa, wah, wal, C_, C3_);
        dim3 grid_p(C_ / 32, C_ / 32);
        split_transpose_kernel<<<grid_p, dim3(32, 8)>>>(Wp, wph, wpl, C_, C_);
    }

    // 2) qkv = x @ W_attn -> bf16 hi/lo directly
    {
        dim3 grid(C3_ / GBN, M_ROWS / GBM);
        gemm_bf16x3_kernel<true><<<grid, 256, SMEM_GEMM>>>(
            xh, xl, wah, wal, nullptr, qkvh, qkvl, M_ROWS, C3_, C_);
    }

    // 3) tensor-core flash attention -> bf16 hi/lo
    {
        dim3 grid(T_ / 128, B_ * H_);
        attn_mma_kernel<<<grid, 256, SMEM_ATTN>>>(qkvh, qkvl, ah, al);
    }

    // 4) y = att @ W_proj (fp32 out)
    {
        dim3 grid(C_ / GBN, M_ROWS / GBM);
        gemm_bf16x3_kernel<false><<<grid, 256, SMEM_GEMM>>>(
            ah, al, wph, wpl, y, nullptr, nullptr, M_ROWS, C_, C_);
    }
}

// round 7
// speedup vs baseline: 2.5455x; 1.0657x over previous
#include <cuda_runtime.h>
#include <cuda_bf16.h>
#include <cstdint>

// Problem dims (fixed per reference)
#define B_  2
#define T_  2048
#define C_  1024
#define H_  16
#define HD_ 64
#define C3_ 3072
#define M_ROWS (B_ * T_)   // 4096

// ---------------------------------------------------------------------------
// Scratch (allocation-free rule: device globals)
// ---------------------------------------------------------------------------
__device__ __nv_bfloat16 g_qkvh[M_ROWS * C3_];   // qkv hi  [4096, 3072]
__device__ __nv_bfloat16 g_qkvl[M_ROWS * C3_];   // qkv lo
__device__ __nv_bfloat16 g_xh[M_ROWS * C_];
__device__ __nv_bfloat16 g_xl[M_ROWS * C_];
__device__ __nv_bfloat16 g_wah[C3_ * C_];        // W_attn^T split [N=3072, K=1024]
__device__ __nv_bfloat16 g_wal[C3_ * C_];
__device__ __nv_bfloat16 g_wph[C_ * C_];         // W_proj^T split [N=1024, K=1024]
__device__ __nv_bfloat16 g_wpl[C_ * C_];
__device__ __nv_bfloat16 g_ah[M_ROWS * C_];      // attention out hi
__device__ __nv_bfloat16 g_al[M_ROWS * C_];      // attention out lo

// ---------------------------------------------------------------------------
__device__ __forceinline__ uint32_t smem_u32(const void* p) {
    uint32_t a;
    asm("{ .reg .u64 t; cvta.to.shared.u64 t, %1; cvt.u32.u64 %0, t; }" : "=r"(a) : "l"(p));
    return a;
}
__device__ __forceinline__ void cp_async16(uint32_t saddr, const void* gaddr) {
    asm volatile("cp.async.cg.shared.global [%0], [%1], 16;" :: "r"(saddr), "l"(gaddr));
}
__device__ __forceinline__ void cp_commit() {
    asm volatile("cp.async.commit_group;" ::: "memory");
}
template <int N>
__device__ __forceinline__ void cp_wait() {
    asm volatile("cp.async.wait_group %0;" :: "n"(N) : "memory");
}
__device__ __forceinline__ void ldm_x4(uint32_t& r0, uint32_t& r1, uint32_t& r2, uint32_t& r3,
                                       uint32_t addr) {
    asm volatile("ldmatrix.sync.aligned.m8n8.x4.shared.b16 {%0,%1,%2,%3}, [%4];"
                 : "=r"(r0), "=r"(r1), "=r"(r2), "=r"(r3) : "r"(addr));
}
__device__ __forceinline__ void ldm_x4_t(uint32_t& r0, uint32_t& r1, uint32_t& r2, uint32_t& r3,
                                         uint32_t addr) {
    asm volatile("ldmatrix.sync.aligned.m8n8.x4.trans.shared.b16 {%0,%1,%2,%3}, [%4];"
                 : "=r"(r0), "=r"(r1), "=r"(r2), "=r"(r3) : "r"(addr));
}
__device__ __forceinline__ void mma_bf16(float* c, uint32_t a0, uint32_t a1, uint32_t a2,
                                         uint32_t a3, uint32_t b0, uint32_t b1) {
    asm volatile(
        "mma.sync.aligned.m16n8k16.row.col.f32.bf16.bf16.f32 "
        "{%0,%1,%2,%3}, {%4,%5,%6,%7}, {%8,%9}, {%0,%1,%2,%3};"
        : "+f"(c[0]), "+f"(c[1]), "+f"(c[2]), "+f"(c[3])
        : "r"(a0), "r"(a1), "r"(a2), "r"(a3), "r"(b0), "r"(b1));
}
__device__ __forceinline__ uint32_t pack_bf16(float lo_elem, float hi_elem) {
    __nv_bfloat162 t = __floats2bfloat162_rn(lo_elem, hi_elem);
    return *(uint32_t*)&t;
}
__device__ __forceinline__ float bf16_residual(float v) {
    return v - __bfloat162float(__float2bfloat16(v));
}

// ---------------------------------------------------------------------------
// Split fp32 -> (hi, lo) bf16
// ---------------------------------------------------------------------------
__global__ __launch_bounds__(256) void split_kernel(
    const float* __restrict__ in, __nv_bfloat16* __restrict__ hi,
    __nv_bfloat16* __restrict__ lo, int n4)
{
    int i = blockIdx.x * blockDim.x + threadIdx.x;
    if (i >= n4) return;
    float4 v = ((const float4*)in)[i];
    __nv_bfloat16 h0 = __float2bfloat16(v.x), h1 = __float2bfloat16(v.y);
    __nv_bfloat16 h2 = __float2bfloat16(v.z), h3 = __float2bfloat16(v.w);
    __nv_bfloat16 l0 = __float2bfloat16(v.x - __bfloat162float(h0));
    __nv_bfloat16 l1 = __float2bfloat16(v.y - __bfloat162float(h1));
    __nv_bfloat16 l2 = __float2bfloat16(v.z - __bfloat162float(h2));
    __nv_bfloat16 l3 = __float2bfloat16(v.w - __bfloat162float(h3));
    __nv_bfloat162* ph = (__nv_bfloat162*)hi + i * 2;
    __nv_bfloat162* pl = (__nv_bfloat162*)lo + i * 2;
    ph[0] = __nv_bfloat162{h0, h1}; ph[1] = __nv_bfloat162{h2, h3};
    pl[0] = __nv_bfloat162{l0, l1}; pl[1] = __nv_bfloat162{l2, l3};
}

// Split + transpose: in [K,N] fp32 -> hiT/loT [N,K] bf16
__global__ __launch_bounds__(256) void split_transpose_kernel(
    const float* __restrict__ in, __nv_bfloat16* __restrict__ hiT,
    __nv_bfloat16* __restrict__ loT, int K, int N)
{
    __shared__ float t[32][33];
    int n0 = blockIdx.x * 32, k0 = blockIdx.y * 32;
    int tx = threadIdx.x, ty = threadIdx.y;   // 32 x 8
#pragma unroll
    for (int i = 0; i < 32; i += 8)
        t[ty + i][tx] = in[(size_t)(k0 + ty + i) * N + n0 + tx];
    __syncthreads();
#pragma unroll
    for (int i = 0; i < 32; i += 8) {
        float v = t[tx][ty + i];
        __nv_bfloat16 h = __float2bfloat16(v);
        __nv_bfloat16 l = __float2bfloat16(v - __bfloat162float(h));
        size_t o = (size_t)(n0 + ty + i) * K + k0 + tx;
        hiT[o] = h; loT[o] = l;
    }
}

// ---------------------------------------------------------------------------
// bf16x3 GEMM via mma.sync:  C[M,N] = A[M,K] @ Bt[N,K]^T
// 128x128 tile, BK=32, 256 threads, double-buffered cp.async.
// __launch_bounds__(256, 2): 2 CTAs/SM (regs <= 128); B fragments chunked
// (2 n8-tiles live at a time) to keep register pressure down.
// ---------------------------------------------------------------------------
#define GBM 128
#define GBN 128
#define GBK 32
#define LDT 40
#define TILE_B (128 * LDT * 2)
#define STAGE_B (4 * TILE_B)
#define SMEM_GEMM (2 * STAGE_B)

template <bool SPLIT>
__global__ __launch_bounds__(256, 2) void gemm_bf16x3_kernel(
    const __nv_bfloat16* __restrict__ Ah, const __nv_bfloat16* __restrict__ Al,
    const __nv_bfloat16* __restrict__ Bh, const __nv_bfloat16* __restrict__ Bl,
    float* __restrict__ Cm, __nv_bfloat16* __restrict__ Ch,
    __nv_bfloat16* __restrict__ Cl, int M, int N, int K)
{
    extern __shared__ char smem[];
    const uint32_t sb = smem_u32(smem);
    const int tid = threadIdx.x;
    const int wid = tid >> 5, lane = tid & 31;
    const int warp_m = wid >> 1;
    const int warp_n = wid & 1;
    const int m0 = blockIdx.y * GBM;
    const int n0 = blockIdx.x * GBN;

    const __nv_bfloat16* gsrc[4] = {Ah, Al, Bh, Bl};
    const int gbase[4] = {m0, m0, n0, n0};

    float acc[2][8][4];
#pragma unroll
    for (int i = 0; i < 2; i++)
#pragma unroll
        for (int j = 0; j < 8; j++)
#pragma unroll
            for (int q = 0; q < 4; q++) acc[i][j][q] = 0.f;

    auto load_stage = [&](int s, int ch) {
        const size_t koff = (size_t)ch * GBK;
        uint32_t sbase = sb + s * STAGE_B;
#pragma unroll
        for (int t4 = 0; t4 < 4; t4++) {
            const __nv_bfloat16* src = gsrc[t4];
            uint32_t tb = sbase + t4 * TILE_B;
#pragma unroll
            for (int i = 0; i < 2; i++) {
                int chunk = tid + i * 256;
                int row = chunk >> 2, seg = chunk & 3;
                cp_async16(tb + (uint32_t)(row * LDT + seg * 8) * 2,
                           src + (size_t)(gbase[t4] + row) * K + koff + seg * 8);
            }
        }
    };

    const int lrow = lane & 15;
    const int lcol = (lane >> 4) << 3;

    auto compute_stage = [&](int s) {
        uint32_t sbase = sb + s * STAGE_B;
        uint32_t sAh = sbase, sAl = sbase + TILE_B;
        uint32_t sBh = sbase + 2 * TILE_B, sBl = sbase + 3 * TILE_B;
#pragma unroll
        for (int ks = 0; ks < 2; ks++) {
            const int k0 = ks * 16;
            uint32_t ahf[2][4], alf[2][4];
#pragma unroll
            for (int mi = 0; mi < 2; mi++) {
                int r = warp_m * 32 + mi * 16 + lrow;
                uint32_t off = (uint32_t)(r * LDT + k0 + lcol) * 2;
                ldm_x4(ahf[mi][0], ahf[mi][1], ahf[mi][2], ahf[mi][3], sAh + off);
                ldm_x4(alf[mi][0], alf[mi][1], alf[mi][2], alf[mi][3], sAl + off);
            }
            // B chunked: only 2 n8-tiles (hi+lo) live at once -> low reg pressure
#pragma unroll
            for (int nt = 0; nt < 4; nt++) {
                int r = warp_n * 64 + nt * 16 + lrow;
                uint32_t off = (uint32_t)(r * LDT + k0 + lcol) * 2;
                uint32_t bh0, bh1, bh2, bh3, bl0, bl1, bl2, bl3;
                ldm_x4(bh0, bh1, bh2, bh3, sBh + off);
                ldm_x4(bl0, bl1, bl2, bl3, sBl + off);
#pragma unroll
                for (int mi = 0; mi < 2; mi++) {
                    float* c0 = acc[mi][nt * 2];
                    float* c1 = acc[mi][nt * 2 + 1];
                    mma_bf16(c0, ahf[mi][0], ahf[mi][1], ahf[mi][2], ahf[mi][3], bh0, bh2);
                    mma_bf16(c1, ahf[mi][0], ahf[mi][1], ahf[mi][2], ahf[mi][3], bh1, bh3);
                    mma_bf16(c0, ahf[mi][0], ahf[mi][1], ahf[mi][2], ahf[mi][3], bl0, bl2);
                    mma_bf16(c1, ahf[mi][0], ahf[mi][1], ahf[mi][2], ahf[mi][3], bl1, bl3);
                    mma_bf16(c0, alf[mi][0], alf[mi][1], alf[mi][2], alf[mi][3], bh0, bh2);
                    mma_bf16(c1, alf[mi][0], alf[mi][1], alf[mi][2], alf[mi][3], bh1, bh3);
                }
            }
        }
    };

    const int nch = K / GBK;
    load_stage(0, 0);
    cp_commit();
    for (int ch = 0; ch < nch; ch++) {
        if (ch + 1 < nch) {
            load_stage((ch + 1) & 1, ch + 1);
            cp_commit();
            cp_wait<1>();
        } else {
            cp_wait<0>();
        }
        __syncthreads();
        compute_stage(ch & 1);
        __syncthreads();
    }

    const int gid = lane >> 2;
    const int tig = lane & 3;
#pragma unroll
    for (int mi = 0; mi < 2; mi++) {
        int rbase = m0 + warp_m * 32 + mi * 16 + gid;
#pragma unroll
        for (int ni = 0; ni < 8; ni++) {
            int col = n0 + warp_n * 64 + ni * 8 + tig * 2;
            if (SPLIT) {
                float v0 = acc[mi][ni][0], v1 = acc[mi][ni][1];
                float v2 = acc[mi][ni][2], v3 = acc[mi][ni][3];
                *(uint32_t*)(Ch + (size_t)rbase * N + col) = pack_bf16(v0, v1);
                *(uint32_t*)(Cl + (size_t)rbase * N + col) =
                    pack_bf16(bf16_residual(v0), bf16_residual(v1));
                *(uint32_t*)(Ch + (size_t)(rbase + 8) * N + col) = pack_bf16(v2, v3);
                *(uint32_t*)(Cl + (size_t)(rbase + 8) * N + col) =
                    pack_bf16(bf16_residual(v2), bf16_residual(v3));
            } else {
                float* p0 = Cm + (size_t)rbase * N + col;
                float* p1 = Cm + (size_t)(rbase + 8) * N + col;
                p0[0] = acc[mi][ni][0]; p0[1] = acc[mi][ni][1];
                p1[0] = acc[mi][ni][2]; p1[1] = acc[mi][ni][3];
            }
        }
    }
}

// ---------------------------------------------------------------------------
// Tensor-core flash attention (bf16x3), causal + column-0 emphasis.
// Grid (T/128, B*H), 256 threads. 128 q-rows per CTA, 64 k-cols per iter.
// ---------------------------------------------------------------------------
#define AT_LD 72
#define AT_QT_B (128 * AT_LD * 2)          // 18432 per q tile (hi or lo)
#define AT_KV_T (64 * AT_LD * 2)           // 9216 per kv tile
#define AT_STG  (4 * AT_KV_T)              // Kh,Kl,Vh,Vl
#define SMEM_ATTN (2 * AT_QT_B + 2 * AT_STG)   // 110592

__global__ __launch_bounds__(256, 1) void attn_mma_kernel(
    const __nv_bfloat16* __restrict__ qkvh, const __nv_bfloat16* __restrict__ qkvl,
    __nv_bfloat16* __restrict__ ah, __nv_bfloat16* __restrict__ al)
{
    extern __shared__ char smem[];
    const uint32_t sb = smem_u32(smem);
    const int tid = threadIdx.x;
    const int wid = tid >> 5, lane = tid & 31;
    const int qt = blockIdx.x;
    const int bh = blockIdx.y;
    const int b = bh >> 4, h = bh & 15;
    const int q0 = qt * 128;

    const uint32_t sQh = sb, sQl = sb + AT_QT_B;
    const uint32_t stg0 = sb + 2 * AT_QT_B;

    // --- load Q (hi/lo) ---
#pragma unroll
    for (int i = 0; i < 8; i++) {
        int chunk = tid + i * 256;      // 0..2047
        int isLo = chunk >> 10;
        int c2 = chunk & 1023;
        int row = c2 >> 3, seg = c2 & 7;
        const __nv_bfloat16* src = (isLo ? qkvl : qkvh) +
            (size_t)(b * T_ + q0 + row) * C3_ + h * HD_ + seg * 8;
        cp_async16((isLo ? sQl : sQh) + (uint32_t)(row * AT_LD + seg * 8) * 2, src);
    }
    cp_commit();

    auto load_kv = [&](int s, int it) {
        const int k0 = it * 64;
        uint32_t sbase = stg0 + s * AT_STG;
#pragma unroll
        for (int i = 0; i < 8; i++) {
            int chunk = tid + i * 256;      // 0..2047
            int t4 = chunk >> 9;            // 0=Kh 1=Kl 2=Vh 3=Vl
            int c2 = chunk & 511;
            int row = c2 >> 3, seg = c2 & 7;
            const __nv_bfloat16* base = (t4 & 1) ? qkvl : qkvh;
            size_t coloff = (t4 < 2) ? (size_t)(C_ + h * HD_) : (size_t)(2 * C_ + h * HD_);
            cp_async16(sbase + t4 * AT_KV_T + (uint32_t)(row * AT_LD + seg * 8) * 2,
                       base + (size_t)(b * T_ + k0 + row) * C3_ + coloff + seg * 8);
        }
    };
    load_kv(0, 0);
    cp_commit();
    cp_wait<0>();
    __syncthreads();

    const int lrow = lane & 15;
    const int lcol = (lane >> 4) << 3;
    const int gid = lane >> 2;
    const int tig = lane & 3;

    // --- Q fragments (persistent) ---
    uint32_t qh[4][4], ql[4][4];
#pragma unroll
    for (int kt = 0; kt < 4; kt++) {
        uint32_t off = (uint32_t)((wid * 16 + lrow) * AT_LD + kt * 16 + lcol) * 2;
        ldm_x4(qh[kt][0], qh[kt][1], qh[kt][2], qh[kt][3], sQh + off);
        ldm_x4(ql[kt][0], ql[kt][1], ql[kt][2], ql[kt][3], sQl + off);
    }

    float o[8][4];
#pragma unroll
    for (int i = 0; i < 8; i++)
#pragma unroll
        for (int j = 0; j < 4; j++) o[i][j] = 0.f;
    float m0r = -1e30f, m1r = -1e30f, l0r = 0.f, l1r = 0.f;

    const int niters = 2 * qt + 2;
    for (int it = 0; it < niters; it++) {
        if (it + 1 < niters) {
            load_kv((it + 1) & 1, it + 1);
            cp_commit();
            cp_wait<1>();
        } else {
            cp_wait<0>();
        }
        __syncthreads();

        const uint32_t s_ = stg0 + (it & 1) * AT_STG;
        const uint32_t sKh = s_, sKl = s_ + AT_KV_T;
        const uint32_t sVh = s_ + 2 * AT_KV_T, sVl = s_ + 3 * AT_KV_T;
        const int k0 = it * 64;
        const bool active = (q0 + wid * 16 + 15 >= k0);

        if (active) {
            // ---- S = Q @ K^T (3-term) ----
            float s[8][4];
#pragma unroll
            for (int i = 0; i < 8; i++)
#pragma unroll
                for (int j = 0; j < 4; j++) s[i][j] = 0.f;

#pragma unroll
            for (int kt = 0; kt < 4; kt++) {
#pragma unroll
                for (int np = 0; np < 4; np++) {
                    uint32_t boff = (uint32_t)((np * 16 + lrow) * AT_LD + kt * 16 + lcol) * 2;
                    uint32_t h0, h1, h2, h3, e0, e1, e2, e3;
                    ldm_x4(h0, h1, h2, h3, sKh + boff);
                    ldm_x4(e0, e1, e2, e3, sKl + boff);
                    mma_bf16(s[np * 2],     qh[kt][0], qh[kt][1], qh[kt][2], qh[kt][3], h0, h2);
                    mma_bf16(s[np * 2 + 1], qh[kt][0], qh[kt][1], qh[kt][2], qh[kt][3], h1, h3);
                    mma_bf16(s[np * 2],     qh[kt][0], qh[kt][1], qh[kt][2], qh[kt][3], e0, e2);
                    mma_bf16(s[np * 2 + 1], qh[kt][0], qh[kt][1], qh[kt][2], qh[kt][3], e1, e3);
                    mma_bf16(s[np * 2],     ql[kt][0], ql[kt][1], ql[kt][2], ql[kt][3], h0, h2);
                    mma_bf16(s[np * 2 + 1], ql[kt][0], ql[kt][1], ql[kt][2], ql[kt][3], h1, h3);
                }
            }

            // ---- scale + emphasis + causal mask ----
#pragma unroll
            for (int ni = 0; ni < 8; ni++)
#pragma unroll
                for (int e = 0; e < 4; e++) s[ni][e] *= 0.125f;
            if (it == 0 && tig == 0) { s[0][0] += 1.0f; s[0][2] += 1.0f; }
            const int grow0 = q0 + wid * 16 + gid;
            const int grow1 = grow0 + 8;
            if (k0 + 63 > q0 + wid * 16) {
#pragma unroll
                for (int ni = 0; ni < 8; ni++) {
                    int gc = k0 + ni * 8 + tig * 2;
                    if (gc > grow0)     s[ni][0] = -1e30f;
                    if (gc + 1 > grow0) s[ni][1] = -1e30f;
                    if (gc > grow1)     s[ni][2] = -1e30f;
                    if (gc + 1 > grow1) s[ni][3] = -1e30f;
                }
            }

            // ---- online softmax (rows grow0, grow1) ----
            float mx0 = s[0][0], mx1 = s[0][2];
#pragma unroll
            for (int ni = 0; ni < 8; ni++) {
                mx0 = fmaxf(mx0, fmaxf(s[ni][0], s[ni][1]));
                mx1 = fmaxf(mx1, fmaxf(s[ni][2], s[ni][3]));
            }
            mx0 = fmaxf(mx0, __shfl_xor_sync(0xffffffffu, mx0, 1));
            mx0 = fmaxf(mx0, __shfl_xor_sync(0xffffffffu, mx0, 2));
            mx1 = fmaxf(mx1, __shfl_xor_sync(0xffffffffu, mx1, 1));
            mx1 = fmaxf(mx1, __shfl_xor_sync(0xffffffffu, mx1, 2));
            float mn0 = fmaxf(m0r, mx0), mn1 = fmaxf(m1r, mx1);
            float a0 = __expf(m0r - mn0), a1 = __expf(m1r - mn1);
            m0r = mn0; m1r = mn1;
            float sum0 = 0.f, sum1 = 0.f;
#pragma unroll
            for (int ni = 0; ni < 8; ni++) {
                s[ni][0] = __expf(s[ni][0] - mn0);
                s[ni][1] = __expf(s[ni][1] - mn0);
                s[ni][2] = __expf(s[ni][2] - mn1);
                s[ni][3] = __expf(s[ni][3] - mn1);
                sum0 += s[ni][0] + s[ni][1];
                sum1 += s[ni][2] + s[ni][3];
            }
            sum0 += __shfl_xor_sync(0xffffffffu, sum0, 1);
            sum0 += __shfl_xor_sync(0xffffffffu, sum0, 2);
            sum1 += __shfl_xor_sync(0xffffffffu, sum1, 1);
            sum1 += __shfl_xor_sync(0xffffffffu, sum1, 2);
            l0r = l0r * a0 + sum0;
            l1r = l1r * a1 + sum1;

            // ---- rescale O ----
#pragma unroll
            for (int ni = 0; ni < 8; ni++) {
                o[ni][0] *= a0; o[ni][1] *= a0;
                o[ni][2] *= a1; o[ni][3] *= a1;
            }

            // ---- PV (3-term): P hi/lo from s, V via ldmatrix.trans ----
#pragma unroll
            for (int kt = 0; kt < 4; kt++) {
                uint32_t ph[4], pl[4];
                {
                    float v0 = s[2 * kt][0], v1 = s[2 * kt][1];
                    float v2 = s[2 * kt][2], v3 = s[2 * kt][3];
                    float w0 = s[2 * kt + 1][0], w1 = s[2 * kt + 1][1];
                    float w2 = s[2 * kt + 1][2], w3 = s[2 * kt + 1][3];
                    ph[0] = pack_bf16(v0, v1); ph[1] = pack_bf16(v2, v3);
                    ph[2] = pack_bf16(w0, w1); ph[3] = pack_bf16(w2, w3);
                    pl[0] = pack_bf16(bf16_residual(v0), bf16_residual(v1));
                    pl[1] = pack_bf16(bf16_residual(v2), bf16_residual(v3));
                    pl[2] = pack_bf16(bf16_residual(w0), bf16_residual(w1));
                    pl[3] = pack_bf16(bf16_residual(w2), bf16_residual(w3));
                }
#pragma unroll
                for (int dp = 0; dp < 4; dp++) {
                    uint32_t voff = (uint32_t)((kt * 16 + lrow) * AT_LD + dp * 16 + lcol) * 2;
                    uint32_t h0, h1, h2, h3, e0, e1, e2, e3;
                    ldm_x4_t(h0, h1, h2, h3, sVh + voff);
                    ldm_x4_t(e0, e1, e2, e3, sVl + voff);
                    mma_bf16(o[dp * 2],     ph[0], ph[1], ph[2], ph[3], h0, h1);
                    mma_bf16(o[dp * 2 + 1], ph[0], ph[1], ph[2], ph[3], h2, h3);
                    mma_bf16(o[dp * 2],     ph[0], ph[1], ph[2], ph[3], e0, e1);
                    mma_bf16(o[dp * 2 + 1], ph[0], ph[1], ph[2], ph[3], e2, e3);
                    mma_bf16(o[dp * 2],     pl[0], pl[1], pl[2], pl[3], h0, h1);
                    mma_bf16(o[dp * 2 + 1], pl[0], pl[1], pl[2], pl[3], h2, h3);
                }
            }
        }
    }

    // ---- epilogue: normalize, split hi/lo, store ----
    const float inv0 = 1.f / l0r, inv1 = 1.f / l1r;
    const int grow0 = q0 + wid * 16 + gid;
    const size_t r0o = (size_t)(b * T_ + grow0) * C_;
    const size_t r1o = (size_t)(b * T_ + grow0 + 8) * C_;
#pragma unroll
    for (int ni = 0; ni < 8; ni++) {
        int col = h * HD_ + ni * 8 + tig * 2;
        float v0 = o[ni][0] * inv0, v1 = o[ni][1] * inv0;
        float v2 = o[ni][2] * inv1, v3 = o[ni][3] * inv1;
        *(uint32_t*)(ah + r0o + col) = pack_bf16(v0, v1);
        *(uint32_t*)(al + r0o + col) = pack_bf16(bf16_residual(v0), bf16_residual(v1));
        *(uint32_t*)(ah + r1o + col) = pack_bf16(v2, v3);
        *(uint32_t*)(al + r1o + col) = pack_bf16(bf16_residual(v2), bf16_residual(v3));
    }
}

// ---------------------------------------------------------------------------
extern "C" void kernel_launch(void* const* d_in, const int* in_sizes, int n_in,
                              void* d_out, int out_size)
{
    const float* x  = (const float*)d_in[0];
    const float* Wa = (const float*)d_in[1];
    const float* Wp = (const float*)d_in[2];
    float* y = (float*)d_out;

    __nv_bfloat16 *qkvh, *qkvl, *xh, *xl, *wah, *wal, *wph, *wpl, *ah, *al;
    cudaGetSymbolAddress((void**)&qkvh, g_qkvh);
    cudaGetSymbolAddress((void**)&qkvl, g_qkvl);
    cudaGetSymbolAddress((void**)&xh, g_xh);
    cudaGetSymbolAddress((void**)&xl, g_xl);
    cudaGetSymbolAddress((void**)&wah, g_wah);
    cudaGetSymbolAddress((void**)&wal, g_wal);
    cudaGetSymbolAddress((void**)&wph, g_wph);
    cudaGetSymbolAddress((void**)&wpl, g_wpl);
    cudaGetSymbolAddress((void**)&ah, g_ah);
    cudaGetSymbolAddress((void**)&al, g_al);

    cudaFuncSetAttribute(gemm_bf16x3_kernel<true>,
                         cudaFuncAttributeMaxDynamicSharedMemorySize, SMEM_GEMM);
    cudaFuncSetAttribute(gemm_bf16x3_kernel<false>,
                         cudaFuncAttributeMaxDynamicSharedMemorySize, SMEM_GEMM);
    cudaFuncSetAttribute(attn_mma_kernel,
                         cudaFuncAttributeMaxDynamicSharedMemorySize, SMEM_ATTN);

    // 1) splits
    {
        int n4 = M_ROWS * C_ / 4;
        split_kernel<<<(n4 + 255) / 256, 256>>>(x, xh, xl, n4);
        dim3 grid_a(C3_ / 32, C_ / 32);
        split_transpose_kernel<<<grid_a, dim3(32, 8)>>>(Wa, wah, wal, C_, C3_);
        dim3 grid_p(C_ / 32, C_ / 32);
        split_transpose_kernel<<<grid_p, dim3(32, 8)>>>(Wp, wph, wpl, C_, C_);
    }

    // 2) qkv = x @ W_attn -> bf16 hi/lo directly
    {
        dim3 grid(C3_ / GBN, M_ROWS / GBM);
        gemm_bf16x3_kernel<true><<<grid, 256, SMEM_GEMM>>>(
            xh, xl, wah, wal, nullptr, qkvh, qkvl, M_ROWS, C3_, C_);
    }

    // 3) tensor-core flash attention -> bf16 hi/lo
    {
        dim3 grid(T_ / 128, B_ * H_);
        attn_mma_kernel<<<grid, 256, SMEM_ATTN>>>(qkvh, qkvl, ah, al);
    }

    // 4) y = att @ W_proj (fp32 out)
    {
        dim3 grid(C_ / GBN, M_ROWS / GBM);
        gemm_bf16x3_kernel<false><<<grid, 256, SMEM_GEMM>>>(
            ah, al, wph, wpl, y, nullptr, nullptr, M_ROWS, C_, C_);
    }
}

// round 8
// speedup vs baseline: 3.5360x; 1.3891x over previous
#include <cuda_runtime.h>
#include <cuda_fp16.h>
#include <cstdint>

// Problem dims (fixed per reference)
#define B_  2
#define T_  2048
#define C_  1024
#define H_  16
#define HD_ 64
#define C3_ 3072
#define M_ROWS (B_ * T_)   // 4096

// ---------------------------------------------------------------------------
// Scratch (allocation-free rule: device globals)   fp16 2-term scheme:
// A operands split hi+lo (exact to 2^-24), B operands single fp16 (err 2^-12)
// ---------------------------------------------------------------------------
__device__ __half g_qkvh[M_ROWS * C3_];   // qkv hi  [4096, 3072]
__device__ __half g_qkvl[M_ROWS * C3_];   // qkv lo  (only Q part consumed)
__device__ __half g_xh[M_ROWS * C_];
__device__ __half g_xl[M_ROWS * C_];
__device__ __half g_wah[C3_ * C_];        // W_attn^T fp16 [N=3072, K=1024]
__device__ __half g_wph[C_ * C_];         // W_proj^T fp16 [N=1024, K=1024]
__device__ __half g_ah[M_ROWS * C_];      // attention out hi
__device__ __half g_al[M_ROWS * C_];      // attention out lo

// ---------------------------------------------------------------------------
__device__ __forceinline__ uint32_t smem_u32(const void* p) {
    uint32_t a;
    asm("{ .reg .u64 t; cvta.to.shared.u64 t, %1; cvt.u32.u64 %0, t; }" : "=r"(a) : "l"(p));
    return a;
}
__device__ __forceinline__ void cp_async16(uint32_t saddr, const void* gaddr) {
    asm volatile("cp.async.cg.shared.global [%0], [%1], 16;" :: "r"(saddr), "l"(gaddr));
}
__device__ __forceinline__ void cp_commit() {
    asm volatile("cp.async.commit_group;" ::: "memory");
}
template <int N>
__device__ __forceinline__ void cp_wait() {
    asm volatile("cp.async.wait_group %0;" :: "n"(N) : "memory");
}
__device__ __forceinline__ void ldm_x4(uint32_t& r0, uint32_t& r1, uint32_t& r2, uint32_t& r3,
                                       uint32_t addr) {
    asm volatile("ldmatrix.sync.aligned.m8n8.x4.shared.b16 {%0,%1,%2,%3}, [%4];"
                 : "=r"(r0), "=r"(r1), "=r"(r2), "=r"(r3) : "r"(addr));
}
__device__ __forceinline__ void ldm_x4_t(uint32_t& r0, uint32_t& r1, uint32_t& r2, uint32_t& r3,
                                         uint32_t addr) {
    asm volatile("ldmatrix.sync.aligned.m8n8.x4.trans.shared.b16 {%0,%1,%2,%3}, [%4];"
                 : "=r"(r0), "=r"(r1), "=r"(r2), "=r"(r3) : "r"(addr));
}
__device__ __forceinline__ void mma_f16(float* c, uint32_t a0, uint32_t a1, uint32_t a2,
                                        uint32_t a3, uint32_t b0, uint32_t b1) {
    asm volatile(
        "mma.sync.aligned.m16n8k16.row.col.f32.f16.f16.f32 "
        "{%0,%1,%2,%3}, {%4,%5,%6,%7}, {%8,%9}, {%0,%1,%2,%3};"
        : "+f"(c[0]), "+f"(c[1]), "+f"(c[2]), "+f"(c[3])
        : "r"(a0), "r"(a1), "r"(a2), "r"(a3), "r"(b0), "r"(b1));
}
__device__ __forceinline__ uint32_t pack_f16(float lo_elem, float hi_elem) {
    __half2 t = __floats2half2_rn(lo_elem, hi_elem);
    return *(uint32_t*)&t;
}
__device__ __forceinline__ float f16_residual(float v) {
    return v - __half2float(__float2half(v));
}

// ---------------------------------------------------------------------------
// Split fp32 -> (hi, lo) fp16
// ---------------------------------------------------------------------------
__global__ __launch_bounds__(256) void split_kernel(
    const float* __restrict__ in, __half* __restrict__ hi,
    __half* __restrict__ lo, int n4)
{
    int i = blockIdx.x * blockDim.x + threadIdx.x;
    if (i >= n4) return;
    float4 v = ((const float4*)in)[i];
    float h0 = __half2float(__float2half(v.x));
    float h1 = __half2float(__float2half(v.y));
    float h2 = __half2float(__float2half(v.z));
    float h3 = __half2float(__float2half(v.w));
    uint32_t* ph = (uint32_t*)hi + i * 2;
    uint32_t* pl = (uint32_t*)lo + i * 2;
    ph[0] = pack_f16(v.x, v.y);  ph[1] = pack_f16(v.z, v.w);
    pl[0] = pack_f16(v.x - h0, v.y - h1);
    pl[1] = pack_f16(v.z - h2, v.w - h3);
}

// Transpose + fp16 round: in [K,N] fp32 -> hiT [N,K] fp16 (no residual)
__global__ __launch_bounds__(256) void transpose_f16_kernel(
    const float* __restrict__ in, __half* __restrict__ hiT, int K, int N)
{
    __shared__ float t[32][33];
    int n0 = blockIdx.x * 32, k0 = blockIdx.y * 32;
    int tx = threadIdx.x, ty = threadIdx.y;   // 32 x 8
#pragma unroll
    for (int i = 0; i < 32; i += 8)
        t[ty + i][tx] = in[(size_t)(k0 + ty + i) * N + n0 + tx];
    __syncthreads();
#pragma unroll
    for (int i = 0; i < 32; i += 8) {
        size_t o = (size_t)(n0 + ty + i) * K + k0 + tx;
        hiT[o] = __float2half(t[tx][ty + i]);
    }
}

// ---------------------------------------------------------------------------
// fp16 2-term GEMM via mma.sync:  C[M,N] = (Ah+Al)[M,K] @ Bh[N,K]^T
// 128x128 tile, BK=32, 256 threads, double-buffered cp.async, 2 CTAs/SM.
// ---------------------------------------------------------------------------
#define GBM 128
#define GBN 128
#define GBK 32
#define LDT 40
#define TILE_B (128 * LDT * 2)
#define STAGE_B (3 * TILE_B)           // Ah, Al, Bh
#define SMEM_GEMM (2 * STAGE_B)        // 61440

template <bool SPLIT>
__global__ __launch_bounds__(256, 2) void gemm_f16x2_kernel(
    const __half* __restrict__ Ah, const __half* __restrict__ Al,
    const __half* __restrict__ Bh,
    float* __restrict__ Cm, __half* __restrict__ Ch,
    __half* __restrict__ Cl, int M, int N, int K)
{
    extern __shared__ char smem[];
    const uint32_t sb = smem_u32(smem);
    const int tid = threadIdx.x;
    const int wid = tid >> 5, lane = tid & 31;
    const int warp_m = wid >> 1;
    const int warp_n = wid & 1;
    const int m0 = blockIdx.y * GBM;
    const int n0 = blockIdx.x * GBN;

    const __half* gsrc[3] = {Ah, Al, Bh};
    const int gbase[3] = {m0, m0, n0};

    float acc[2][8][4];
#pragma unroll
    for (int i = 0; i < 2; i++)
#pragma unroll
        for (int j = 0; j < 8; j++)
#pragma unroll
            for (int q = 0; q < 4; q++) acc[i][j][q] = 0.f;

    auto load_stage = [&](int s, int ch) {
        const size_t koff = (size_t)ch * GBK;
        uint32_t sbase = sb + s * STAGE_B;
#pragma unroll
        for (int i = 0; i < 6; i++) {
            int chunk = tid + i * 256;          // 0..1535
            int t3 = chunk >> 9;                // tile 0..2
            int c2 = chunk & 511;
            int row = c2 >> 2, seg = c2 & 3;
            cp_async16(sbase + t3 * TILE_B + (uint32_t)(row * LDT + seg * 8) * 2,
                       gsrc[t3] + (size_t)(gbase[t3] + row) * K + koff + seg * 8);
        }
    };

    const int lrow = lane & 15;
    const int lcol = (lane >> 4) << 3;

    auto compute_stage = [&](int s) {
        uint32_t sbase = sb + s * STAGE_B;
        uint32_t sAh = sbase, sAl = sbase + TILE_B;
        uint32_t sBh = sbase + 2 * TILE_B;
#pragma unroll
        for (int ks = 0; ks < 2; ks++) {
            const int k0 = ks * 16;
            uint32_t ahf[2][4], alf[2][4];
#pragma unroll
            for (int mi = 0; mi < 2; mi++) {
                int r = warp_m * 32 + mi * 16 + lrow;
                uint32_t off = (uint32_t)(r * LDT + k0 + lcol) * 2;
                ldm_x4(ahf[mi][0], ahf[mi][1], ahf[mi][2], ahf[mi][3], sAh + off);
                ldm_x4(alf[mi][0], alf[mi][1], alf[mi][2], alf[mi][3], sAl + off);
            }
#pragma unroll
            for (int nt = 0; nt < 4; nt++) {
                int r = warp_n * 64 + nt * 16 + lrow;
                uint32_t off = (uint32_t)(r * LDT + k0 + lcol) * 2;
                uint32_t bh0, bh1, bh2, bh3;
                ldm_x4(bh0, bh1, bh2, bh3, sBh + off);
#pragma unroll
                for (int mi = 0; mi < 2; mi++) {
                    float* c0 = acc[mi][nt * 2];
                    float* c1 = acc[mi][nt * 2 + 1];
                    mma_f16(c0, ahf[mi][0], ahf[mi][1], ahf[mi][2], ahf[mi][3], bh0, bh2);
                    mma_f16(c1, ahf[mi][0], ahf[mi][1], ahf[mi][2], ahf[mi][3], bh1, bh3);
                    mma_f16(c0, alf[mi][0], alf[mi][1], alf[mi][2], alf[mi][3], bh0, bh2);
                    mma_f16(c1, alf[mi][0], alf[mi][1], alf[mi][2], alf[mi][3], bh1, bh3);
                }
            }
        }
    };

    const int nch = K / GBK;
    load_stage(0, 0);
    cp_commit();
    for (int ch = 0; ch < nch; ch++) {
        if (ch + 1 < nch) {
            load_stage((ch + 1) & 1, ch + 1);
            cp_commit();
            cp_wait<1>();
        } else {
            cp_wait<0>();
        }
        __syncthreads();
        compute_stage(ch & 1);
        __syncthreads();
    }

    const int gid = lane >> 2;
    const int tig = lane & 3;
#pragma unroll
    for (int mi = 0; mi < 2; mi++) {
        int rbase = m0 + warp_m * 32 + mi * 16 + gid;
#pragma unroll
        for (int ni = 0; ni < 8; ni++) {
            int col = n0 + warp_n * 64 + ni * 8 + tig * 2;
            if (SPLIT) {
                float v0 = acc[mi][ni][0], v1 = acc[mi][ni][1];
                float v2 = acc[mi][ni][2], v3 = acc[mi][ni][3];
                *(uint32_t*)(Ch + (size_t)rbase * N + col) = pack_f16(v0, v1);
                *(uint32_t*)(Cl + (size_t)rbase * N + col) =
                    pack_f16(f16_residual(v0), f16_residual(v1));
                *(uint32_t*)(Ch + (size_t)(rbase + 8) * N + col) = pack_f16(v2, v3);
                *(uint32_t*)(Cl + (size_t)(rbase + 8) * N + col) =
                    pack_f16(f16_residual(v2), f16_residual(v3));
            } else {
                float* p0 = Cm + (size_t)rbase * N + col;
                float* p1 = Cm + (size_t)(rbase + 8) * N + col;
                p0[0] = acc[mi][ni][0]; p0[1] = acc[mi][ni][1];
                p1[0] = acc[mi][ni][2]; p1[1] = acc[mi][ni][3];
            }
        }
    }
}

// ---------------------------------------------------------------------------
// fp16 2-term flash attention, causal + column-0 emphasis.
// Q split hi/lo (persistent frags), K/V single fp16. P split in-register.
// Grid (T/128, B*H), 256 threads. qt reversed for tail balance.
// ---------------------------------------------------------------------------
#define AT_LD 72
#define AT_QT_B (128 * AT_LD * 2)          // 18432 per Q tile (hi or lo)
#define AT_KV_T (64 * AT_LD * 2)           // 9216 per KV tile
#define AT_STG  (2 * AT_KV_T)              // Kh, Vh
#define SMEM_ATTN (2 * AT_QT_B + 2 * AT_STG)   // 73728

__global__ __launch_bounds__(256, 1) void attn_mma_kernel(
    const __half* __restrict__ qkvh, const __half* __restrict__ qkvl,
    __half* __restrict__ ah, __half* __restrict__ al)
{
    extern __shared__ char smem[];
    const uint32_t sb = smem_u32(smem);
    const int tid = threadIdx.x;
    const int wid = tid >> 5, lane = tid & 31;
    const int qt = (int)gridDim.x - 1 - (int)blockIdx.x;   // heavy blocks first
    const int bh = blockIdx.y;
    const int b = bh >> 4, h = bh & 15;
    const int q0 = qt * 128;

    const uint32_t sQh = sb, sQl = sb + AT_QT_B;
    const uint32_t stg0 = sb + 2 * AT_QT_B;

    // --- load Q (hi/lo) ---
#pragma unroll
    for (int i = 0; i < 8; i++) {
        int chunk = tid + i * 256;      // 0..2047
        int isLo = chunk >> 10;
        int c2 = chunk & 1023;
        int row = c2 >> 3, seg = c2 & 7;
        const __half* src = (isLo ? qkvl : qkvh) +
            (size_t)(b * T_ + q0 + row) * C3_ + h * HD_ + seg * 8;
        cp_async16((isLo ? sQl : sQh) + (uint32_t)(row * AT_LD + seg * 8) * 2, src);
    }
    cp_commit();

    auto load_kv = [&](int s, int it) {
        const int k0 = it * 64;
        uint32_t sbase = stg0 + s * AT_STG;
#pragma unroll
        for (int i = 0; i < 4; i++) {
            int chunk = tid + i * 256;      // 0..1023
            int t2 = chunk >> 9;            // 0=Kh 1=Vh
            int c2 = chunk & 511;
            int row = c2 >> 3, seg = c2 & 7;
            size_t coloff = (t2 == 0) ? (size_t)(C_ + h * HD_) : (size_t)(2 * C_ + h * HD_);
            cp_async16(sbase + t2 * AT_KV_T + (uint32_t)(row * AT_LD + seg * 8) * 2,
                       qkvh + (size_t)(b * T_ + k0 + row) * C3_ + coloff + seg * 8);
        }
    };
    load_kv(0, 0);
    cp_commit();
    cp_wait<0>();
    __syncthreads();

    const int lrow = lane & 15;
    const int lcol = (lane >> 4) << 3;
    const int gid = lane >> 2;
    const int tig = lane & 3;

    // --- Q fragments (persistent) ---
    uint32_t qh[4][4], ql[4][4];
#pragma unroll
    for (int kt = 0; kt < 4; kt++) {
        uint32_t off = (uint32_t)((wid * 16 + lrow) * AT_LD + kt * 16 + lcol) * 2;
        ldm_x4(qh[kt][0], qh[kt][1], qh[kt][2], qh[kt][3], sQh + off);
        ldm_x4(ql[kt][0], ql[kt][1], ql[kt][2], ql[kt][3], sQl + off);
    }

    float o[8][4];
#pragma unroll
    for (int i = 0; i < 8; i++)
#pragma unroll
        for (int j = 0; j < 4; j++) o[i][j] = 0.f;
    float m0r = -1e30f, m1r = -1e30f, l0r = 0.f, l1r = 0.f;

    const int niters = 2 * qt + 2;
    for (int it = 0; it < niters; it++) {
        if (it + 1 < niters) {
            load_kv((it + 1) & 1, it + 1);
            cp_commit();
            cp_wait<1>();
        } else {
            cp_wait<0>();
        }
        __syncthreads();

        const uint32_t s_ = stg0 + (it & 1) * AT_STG;
        const uint32_t sKh = s_, sVh = s_ + AT_KV_T;
        const int k0 = it * 64;
        const bool active = (q0 + wid * 16 + 15 >= k0);

        if (active) {
            // ---- S = Q @ K^T (2-term: Qh·K + Ql·K) ----
            float s[8][4];
#pragma unroll
            for (int i = 0; i < 8; i++)
#pragma unroll
                for (int j = 0; j < 4; j++) s[i][j] = 0.f;

#pragma unroll
            for (int kt = 0; kt < 4; kt++) {
#pragma unroll
                for (int np = 0; np < 4; np++) {
                    uint32_t boff = (uint32_t)((np * 16 + lrow) * AT_LD + kt * 16 + lcol) * 2;
                    uint32_t h0, h1, h2, h3;
                    ldm_x4(h0, h1, h2, h3, sKh + boff);
                    mma_f16(s[np * 2],     qh[kt][0], qh[kt][1], qh[kt][2], qh[kt][3], h0, h2);
                    mma_f16(s[np * 2 + 1], qh[kt][0], qh[kt][1], qh[kt][2], qh[kt][3], h1, h3);
                    mma_f16(s[np * 2],     ql[kt][0], ql[kt][1], ql[kt][2], ql[kt][3], h0, h2);
                    mma_f16(s[np * 2 + 1], ql[kt][0], ql[kt][1], ql[kt][2], ql[kt][3], h1, h3);
                }
            }

            // ---- scale + emphasis + causal mask ----
#pragma unroll
            for (int ni = 0; ni < 8; ni++)
#pragma unroll
                for (int e = 0; e < 4; e++) s[ni][e] *= 0.125f;
            if (it == 0 && tig == 0) { s[0][0] += 1.0f; s[0][2] += 1.0f; }
            const int grow0 = q0 + wid * 16 + gid;
            const int grow1 = grow0 + 8;
            if (k0 + 63 > q0 + wid * 16) {
#pragma unroll
                for (int ni = 0; ni < 8; ni++) {
                    int gc = k0 + ni * 8 + tig * 2;
                    if (gc > grow0)     s[ni][0] = -1e30f;
                    if (gc + 1 > grow0) s[ni][1] = -1e30f;
                    if (gc > grow1)     s[ni][2] = -1e30f;
                    if (gc + 1 > grow1) s[ni][3] = -1e30f;
                }
            }

            // ---- online softmax (rows grow0, grow1) ----
            float mx0 = s[0][0], mx1 = s[0][2];
#pragma unroll
            for (int ni = 0; ni < 8; ni++) {
                mx0 = fmaxf(mx0, fmaxf(s[ni][0], s[ni][1]));
                mx1 = fmaxf(mx1, fmaxf(s[ni][2], s[ni][3]));
            }
            mx0 = fmaxf(mx0, __shfl_xor_sync(0xffffffffu, mx0, 1));
            mx0 = fmaxf(mx0, __shfl_xor_sync(0xffffffffu, mx0, 2));
            mx1 = fmaxf(mx1, __shfl_xor_sync(0xffffffffu, mx1, 1));
            mx1 = fmaxf(mx1, __shfl_xor_sync(0xffffffffu, mx1, 2));
            float mn0 = fmaxf(m0r, mx0), mn1 = fmaxf(m1r, mx1);
            float a0 = __expf(m0r - mn0), a1 = __expf(m1r - mn1);
            m0r = mn0; m1r = mn1;
            float sum0 = 0.f, sum1 = 0.f;
#pragma unroll
            for (int ni = 0; ni < 8; ni++) {
                s[ni][0] = __expf(s[ni][0] - mn0);
                s[ni][1] = __expf(s[ni][1] - mn0);
                s[ni][2] = __expf(s[ni][2] - mn1);
                s[ni][3] = __expf(s[ni][3] - mn1);
                sum0 += s[ni][0] + s[ni][1];
                sum1 += s[ni][2] + s[ni][3];
            }
            sum0 += __shfl_xor_sync(0xffffffffu, sum0, 1);
            sum0 += __shfl_xor_sync(0xffffffffu, sum0, 2);
            sum1 += __shfl_xor_sync(0xffffffffu, sum1, 1);
            sum1 += __shfl_xor_sync(0xffffffffu, sum1, 2);
            l0r = l0r * a0 + sum0;
            l1r = l1r * a1 + sum1;

            // ---- rescale O ----
#pragma unroll
            for (int ni = 0; ni < 8; ni++) {
                o[ni][0] *= a0; o[ni][1] *= a0;
                o[ni][2] *= a1; o[ni][3] *= a1;
            }

            // ---- PV (2-term: (Ph+Pl)·V), V via ldmatrix.trans ----
#pragma unroll
            for (int kt = 0; kt < 4; kt++) {
                uint32_t ph[4], pl[4];
                {
                    float v0 = s[2 * kt][0], v1 = s[2 * kt][1];
                    float v2 = s[2 * kt][2], v3 = s[2 * kt][3];
                    float w0 = s[2 * kt + 1][0], w1 = s[2 * kt + 1][1];
                    float w2 = s[2 * kt + 1][2], w3 = s[2 * kt + 1][3];
                    ph[0] = pack_f16(v0, v1); ph[1] = pack_f16(v2, v3);
                    ph[2] = pack_f16(w0, w1); ph[3] = pack_f16(w2, w3);
                    pl[0] = pack_f16(f16_residual(v0), f16_residual(v1));
                    pl[1] = pack_f16(f16_residual(v2), f16_residual(v3));
                    pl[2] = pack_f16(f16_residual(w0), f16_residual(w1));
                    pl[3] = pack_f16(f16_residual(w2), f16_residual(w3));
                }
#pragma unroll
                for (int dp = 0; dp < 4; dp++) {
                    uint32_t voff = (uint32_t)((kt * 16 + lrow) * AT_LD + dp * 16 + lcol) * 2;
                    uint32_t h0, h1, h2, h3;
                    ldm_x4_t(h0, h1, h2, h3, sVh + voff);
                    mma_f16(o[dp * 2],     ph[0], ph[1], ph[2], ph[3], h0, h1);
                    mma_f16(o[dp * 2 + 1], ph[0], ph[1], ph[2], ph[3], h2, h3);
                    mma_f16(o[dp * 2],     pl[0], pl[1], pl[2], pl[3], h0, h1);
                    mma_f16(o[dp * 2 + 1], pl[0], pl[1], pl[2], pl[3], h2, h3);
                }
            }
        }
    }

    // ---- epilogue: normalize, split hi/lo, store ----
    const float inv0 = 1.f / l0r, inv1 = 1.f / l1r;
    const int grow0 = q0 + wid * 16 + gid;
    const size_t r0o = (size_t)(b * T_ + grow0) * C_;
    const size_t r1o = (size_t)(b * T_ + grow0 + 8) * C_;
#pragma unroll
    for (int ni = 0; ni < 8; ni++) {
        int col = h * HD_ + ni * 8 + tig * 2;
        float v0 = o[ni][0] * inv0, v1 = o[ni][1] * inv0;
        float v2 = o[ni][2] * inv1, v3 = o[ni][3] * inv1;
        *(uint32_t*)(ah + r0o + col) = pack_f16(v0, v1);
        *(uint32_t*)(al + r0o + col) = pack_f16(f16_residual(v0), f16_residual(v1));
        *(uint32_t*)(ah + r1o + col) = pack_f16(v2, v3);
        *(uint32_t*)(al + r1o + col) = pack_f16(f16_residual(v2), f16_residual(v3));
    }
}

// ---------------------------------------------------------------------------
extern "C" void kernel_launch(void* const* d_in, const int* in_sizes, int n_in,
                              void* d_out, int out_size)
{
    const float* x  = (const float*)d_in[0];
    const float* Wa = (const float*)d_in[1];
    const float* Wp = (const float*)d_in[2];
    float* y = (float*)d_out;

    __half *qkvh, *qkvl, *xh, *xl, *wah, *wph, *ah, *al;
    cudaGetSymbolAddress((void**)&qkvh, g_qkvh);
    cudaGetSymbolAddress((void**)&qkvl, g_qkvl);
    cudaGetSymbolAddress((void**)&xh, g_xh);
    cudaGetSymbolAddress((void**)&xl, g_xl);
    cudaGetSymbolAddress((void**)&wah, g_wah);
    cudaGetSymbolAddress((void**)&wph, g_wph);
    cudaGetSymbolAddress((void**)&ah, g_ah);
    cudaGetSymbolAddress((void**)&al, g_al);

    cudaFuncSetAttribute(gemm_f16x2_kernel<true>,
                         cudaFuncAttributeMaxDynamicSharedMemorySize, SMEM_GEMM);
    cudaFuncSetAttribute(gemm_f16x2_kernel<false>,
                         cudaFuncAttributeMaxDynamicSharedMemorySize, SMEM_GEMM);
    cudaFuncSetAttribute(attn_mma_kernel,
                         cudaFuncAttributeMaxDynamicSharedMemorySize, SMEM_ATTN);

    // 1) splits / weight transposes
    {
        int n4 = M_ROWS * C_ / 4;
        split_kernel<<<(n4 + 255) / 256, 256>>>(x, xh, xl, n4);
        dim3 grid_a(C3_ / 32, C_ / 32);
        transpose_f16_kernel<<<grid_a, dim3(32, 8)>>>(Wa, wah, C_, C3_);
        dim3 grid_p(C_ / 32, C_ / 32);
        transpose_f16_kernel<<<grid_p, dim3(32, 8)>>>(Wp, wph, C_, C_);
    }

    // 2) qkv = x @ W_attn -> fp16 hi/lo directly
    {
        dim3 grid(C3_ / GBN, M_ROWS / GBM);
        gemm_f16x2_kernel<true><<<grid, 256, SMEM_GEMM>>>(
            xh, xl, wah, nullptr, qkvh, qkvl, M_ROWS, C3_, C_);
    }

    // 3) flash attention -> fp16 hi/lo
    {
        dim3 grid(T_ / 128, B_ * H_);
        attn_mma_kernel<<<grid, 256, SMEM_ATTN>>>(qkvh, qkvl, ah, al);
    }

    // 4) y = att @ W_proj (fp32 out)
    {
        dim3 grid(C_ / GBN, M_ROWS / GBM);
        gemm_f16x2_kernel<false><<<grid, 256, SMEM_GEMM>>>(
            ah, al, wph, y, nullptr, nullptr, M_ROWS, C_, C_);
    }
}

// round 11
// speedup vs baseline: 3.7422x; 1.0583x over previous
#include <cuda_runtime.h>
#include <cuda_fp16.h>
#include <cstdint>

// Problem dims (fixed per reference)
#define B_  2
#define T_  2048
#define C_  1024
#define H_  16
#define HD_ 64
#define C3_ 3072
#define M_ROWS (B_ * T_)   // 4096

// ---------------------------------------------------------------------------
// Scratch (allocation-free rule: device globals)   fp16 2-term scheme:
// A operands split hi+lo (exact to 2^-24), B operands single fp16 (err 2^-12)
// ---------------------------------------------------------------------------
__device__ __half g_qkvh[M_ROWS * C3_];   // qkv hi  [4096, 3072]
__device__ __half g_qkvl[M_ROWS * C3_];   // qkv lo  (only Q part consumed)
__device__ __half g_xh[M_ROWS * C_];
__device__ __half g_xl[M_ROWS * C_];
__device__ __half g_wah[C3_ * C_];        // W_attn^T fp16 [N=3072, K=1024]
__device__ __half g_wph[C_ * C_];         // W_proj^T fp16 [N=1024, K=1024]
__device__ __half g_ah[M_ROWS * C_];      // attention out hi
__device__ __half g_al[M_ROWS * C_];      // attention out lo

// ---------------------------------------------------------------------------
__device__ __forceinline__ uint32_t smem_u32(const void* p) {
    uint32_t a;
    asm("{ .reg .u64 t; cvta.to.shared.u64 t, %1; cvt.u32.u64 %0, t; }" : "=r"(a) : "l"(p));
    return a;
}
__device__ __forceinline__ void cp_async16(uint32_t saddr, const void* gaddr) {
    asm volatile("cp.async.cg.shared.global [%0], [%1], 16;" :: "r"(saddr), "l"(gaddr));
}
__device__ __forceinline__ void cp_commit() {
    asm volatile("cp.async.commit_group;" ::: "memory");
}
template <int N>
__device__ __forceinline__ void cp_wait() {
    asm volatile("cp.async.wait_group %0;" :: "n"(N) : "memory");
}
__device__ __forceinline__ void ldm_x4(uint32_t& r0, uint32_t& r1, uint32_t& r2, uint32_t& r3,
                                       uint32_t addr) {
    asm volatile("ldmatrix.sync.aligned.m8n8.x4.shared.b16 {%0,%1,%2,%3}, [%4];"
                 : "=r"(r0), "=r"(r1), "=r"(r2), "=r"(r3) : "r"(addr));
}
__device__ __forceinline__ void ldm_x4_t(uint32_t& r0, uint32_t& r1, uint32_t& r2, uint32_t& r3,
                                         uint32_t addr) {
    asm volatile("ldmatrix.sync.aligned.m8n8.x4.trans.shared.b16 {%0,%1,%2,%3}, [%4];"
                 : "=r"(r0), "=r"(r1), "=r"(r2), "=r"(r3) : "r"(addr));
}
__device__ __forceinline__ void mma_f16(float* c, uint32_t a0, uint32_t a1, uint32_t a2,
                                        uint32_t a3, uint32_t b0, uint32_t b1) {
    asm volatile(
        "mma.sync.aligned.m16n8k16.row.col.f32.f16.f16.f32 "
        "{%0,%1,%2,%3}, {%4,%5,%6,%7}, {%8,%9}, {%0,%1,%2,%3};"
        : "+f"(c[0]), "+f"(c[1]), "+f"(c[2]), "+f"(c[3])
        : "r"(a0), "r"(a1), "r"(a2), "r"(a3), "r"(b0), "r"(b1));
}
__device__ __forceinline__ uint32_t pack_f16(float lo_elem, float hi_elem) {
    __half2 t = __floats2half2_rn(lo_elem, hi_elem);
    return *(uint32_t*)&t;
}
__device__ __forceinline__ float f16_residual(float v) {
    return v - __half2float(__float2half(v));
}

// ---------------------------------------------------------------------------
// Split fp32 -> (hi, lo) fp16
// ---------------------------------------------------------------------------
__global__ __launch_bounds__(256) void split_kernel(
    const float* __restrict__ in, __half* __restrict__ hi,
    __half* __restrict__ lo, int n4)
{
    int i = blockIdx.x * blockDim.x + threadIdx.x;
    if (i >= n4) return;
    float4 v = ((const float4*)in)[i];
    float h0 = __half2float(__float2half(v.x));
    float h1 = __half2float(__float2half(v.y));
    float h2 = __half2float(__float2half(v.z));
    float h3 = __half2float(__float2half(v.w));
    uint32_t* ph = (uint32_t*)hi + i * 2;
    uint32_t* pl = (uint32_t*)lo + i * 2;
    ph[0] = pack_f16(v.x, v.y);  ph[1] = pack_f16(v.z, v.w);
    pl[0] = pack_f16(v.x - h0, v.y - h1);
    pl[1] = pack_f16(v.z - h2, v.w - h3);
}

// Transpose + fp16 round: in [K,N] fp32 -> hiT [N,K] fp16 (no residual)
__global__ __launch_bounds__(256) void transpose_f16_kernel(
    const float* __restrict__ in, __half* __restrict__ hiT, int K, int N)
{
    __shared__ float t[32][33];
    int n0 = blockIdx.x * 32, k0 = blockIdx.y * 32;
    int tx = threadIdx.x, ty = threadIdx.y;   // 32 x 8
#pragma unroll
    for (int i = 0; i < 32; i += 8)
        t[ty + i][tx] = in[(size_t)(k0 + ty + i) * N + n0 + tx];
    __syncthreads();
#pragma unroll
    for (int i = 0; i < 32; i += 8) {
        size_t o = (size_t)(n0 + ty + i) * K + k0 + tx;
        hiT[o] = __float2half(t[tx][ty + i]);
    }
}

// ---------------------------------------------------------------------------
// fp16 2-term GEMM via mma.sync:  C[M,N] = (Ah+Al)[M,K] @ Bh[N,K]^T
// 128x128 tile, BK=32, 256 threads, 3-stage cp.async pipeline (1 sync/iter).
// ---------------------------------------------------------------------------
#define GBM 128
#define GBN 128
#define GBK 32
#define LDT 40
#define TILE_B (128 * LDT * 2)
#define STAGE_B (3 * TILE_B)           // Ah, Al, Bh
#define NSTG 3
#define SMEM_GEMM (NSTG * STAGE_B)     // 92160

template <bool SPLIT>
__global__ __launch_bounds__(256, 2) void gemm_f16x2_kernel(
    const __half* __restrict__ Ah, const __half* __restrict__ Al,
    const __half* __restrict__ Bh,
    float* __restrict__ Cm, __half* __restrict__ Ch,
    __half* __restrict__ Cl, int M, int N, int K)
{
    extern __shared__ char smem[];
    const uint32_t sb = smem_u32(smem);
    const int tid = threadIdx.x;
    const int wid = tid >> 5, lane = tid & 31;
    const int warp_m = wid >> 1;
    const int warp_n = wid & 1;
    const int m0 = blockIdx.y * GBM;
    const int n0 = blockIdx.x * GBN;

    const __half* gsrc[3] = {Ah, Al, Bh};
    const int gbase[3] = {m0, m0, n0};

    float acc[2][8][4];
#pragma unroll
    for (int i = 0; i < 2; i++)
#pragma unroll
        for (int j = 0; j < 8; j++)
#pragma unroll
            for (int q = 0; q < 4; q++) acc[i][j][q] = 0.f;

    auto load_stage = [&](int s, int ch) {
        const size_t koff = (size_t)ch * GBK;
        uint32_t sbase = sb + s * STAGE_B;
#pragma unroll
        for (int i = 0; i < 6; i++) {
            int chunk = tid + i * 256;          // 0..1535
            int t3 = chunk >> 9;                // tile 0..2
            int c2 = chunk & 511;
            int row = c2 >> 2, seg = c2 & 3;
            cp_async16(sbase + t3 * TILE_B + (uint32_t)(row * LDT + seg * 8) * 2,
                       gsrc[t3] + (size_t)(gbase[t3] + row) * K + koff + seg * 8);
        }
    };

    const int lrow = lane & 15;
    const int lcol = (lane >> 4) << 3;

    auto compute_stage = [&](int s) {
        uint32_t sbase = sb + s * STAGE_B;
        uint32_t sAh = sbase, sAl = sbase + TILE_B;
        uint32_t sBh = sbase + 2 * TILE_B;
#pragma unroll
        for (int ks = 0; ks < 2; ks++) {
            const int k0 = ks * 16;
            uint32_t ahf[2][4], alf[2][4];
#pragma unroll
            for (int mi = 0; mi < 2; mi++) {
                int r = warp_m * 32 + mi * 16 + lrow;
                uint32_t off = (uint32_t)(r * LDT + k0 + lcol) * 2;
                ldm_x4(ahf[mi][0], ahf[mi][1], ahf[mi][2], ahf[mi][3], sAh + off);
                ldm_x4(alf[mi][0], alf[mi][1], alf[mi][2], alf[mi][3], sAl + off);
            }
#pragma unroll
            for (int nt = 0; nt < 4; nt++) {
                int r = warp_n * 64 + nt * 16 + lrow;
                uint32_t off = (uint32_t)(r * LDT + k0 + lcol) * 2;
                uint32_t bh0, bh1, bh2, bh3;
                ldm_x4(bh0, bh1, bh2, bh3, sBh + off);
#pragma unroll
                for (int mi = 0; mi < 2; mi++) {
                    float* c0 = acc[mi][nt * 2];
                    float* c1 = acc[mi][nt * 2 + 1];
                    mma_f16(c0, ahf[mi][0], ahf[mi][1], ahf[mi][2], ahf[mi][3], bh0, bh2);
                    mma_f16(c1, ahf[mi][0], ahf[mi][1], ahf[mi][2], ahf[mi][3], bh1, bh3);
                    mma_f16(c0, alf[mi][0], alf[mi][1], alf[mi][2], alf[mi][3], bh0, bh2);
                    mma_f16(c1, alf[mi][0], alf[mi][1], alf[mi][2], alf[mi][3], bh1, bh3);
                }
            }
        }
    };

    const int nch = K / GBK;     // >= 2 always (K = 1024)
    load_stage(0, 0);
    cp_commit();
    load_stage(1, 1);
    cp_commit();
    for (int ch = 0; ch < nch; ch++) {
        cp_wait<1>();            // load ch complete (ch+1 may be in flight)
        __syncthreads();         // all warps see stage ch%3; prev compute done
        compute_stage(ch % NSTG);
        if (ch + 2 < nch) load_stage((ch + 2) % NSTG, ch + 2);
        cp_commit();
    }

    const int gid = lane >> 2;
    const int tig = lane & 3;
#pragma unroll
    for (int mi = 0; mi < 2; mi++) {
        int rbase = m0 + warp_m * 32 + mi * 16 + gid;
#pragma unroll
        for (int ni = 0; ni < 8; ni++) {
            int col = n0 + warp_n * 64 + ni * 8 + tig * 2;
            if (SPLIT) {
                float v0 = acc[mi][ni][0], v1 = acc[mi][ni][1];
                float v2 = acc[mi][ni][2], v3 = acc[mi][ni][3];
                *(uint32_t*)(Ch + (size_t)rbase * N + col) = pack_f16(v0, v1);
                *(uint32_t*)(Cl + (size_t)rbase * N + col) =
                    pack_f16(f16_residual(v0), f16_residual(v1));
                *(uint32_t*)(Ch + (size_t)(rbase + 8) * N + col) = pack_f16(v2, v3);
                *(uint32_t*)(Cl + (size_t)(rbase + 8) * N + col) =
                    pack_f16(f16_residual(v2), f16_residual(v3));
            } else {
                float* p0 = Cm + (size_t)rbase * N + col;
                float* p1 = Cm + (size_t)(rbase + 8) * N + col;
                p0[0] = acc[mi][ni][0]; p0[1] = acc[mi][ni][1];
                p1[0] = acc[mi][ni][2]; p1[1] = acc[mi][ni][3];
            }
        }
    }
}

// ---------------------------------------------------------------------------
// fp16 2-term flash attention, causal + column-0 emphasis.
// Q split hi/lo (persistent frags), K/V single fp16. P split in-register.
// 3-stage KV pipeline, 1 sync/iter. Grid (T/128, B*H), qt reversed.
// ---------------------------------------------------------------------------
#define AT_LD 72
#define AT_QT_B (128 * AT_LD * 2)          // 18432 per Q tile (hi or lo)
#define AT_KV_T (64 * AT_LD * 2)           // 9216 per KV tile
#define AT_STG  (2 * AT_KV_T)              // Kh, Vh
#define AT_NSTG 3
#define SMEM_ATTN (2 * AT_QT_B + AT_NSTG * AT_STG)   // 92160

__global__ __launch_bounds__(256, 1) void attn_mma_kernel(
    const __half* __restrict__ qkvh, const __half* __restrict__ qkvl,
    __half* __restrict__ ah, __half* __restrict__ al)
{
    extern __shared__ char smem[];
    const uint32_t sb = smem_u32(smem);
    const int tid = threadIdx.x;
    const int wid = tid >> 5, lane = tid & 31;
    const int qt = (int)gridDim.x - 1 - (int)blockIdx.x;   // heavy blocks first
    const int bh = blockIdx.y;
    const int b = bh >> 4, h = bh & 15;
    const int q0 = qt * 128;

    const uint32_t sQh = sb, sQl = sb + AT_QT_B;
    const uint32_t stg0 = sb + 2 * AT_QT_B;

    const int niters = 2 * qt + 2;     // >= 2 always

    // --- load Q (hi/lo), group 0 ---
#pragma unroll
    for (int i = 0; i < 8; i++) {
        int chunk = tid + i * 256;      // 0..2047
        int isLo = chunk >> 10;
        int c2 = chunk & 1023;
        int row = c2 >> 3, seg = c2 & 7;
        const __half* src = (isLo ? qkvl : qkvh) +
            (size_t)(b * T_ + q0 + row) * C3_ + h * HD_ + seg * 8;
        cp_async16((isLo ? sQl : sQh) + (uint32_t)(row * AT_LD + seg * 8) * 2, src);
    }
    cp_commit();

    auto load_kv = [&](int s, int it) {
        const int k0 = it * 64;
        uint32_t sbase = stg0 + s * AT_STG;
#pragma unroll
        for (int i = 0; i < 4; i++) {
            int chunk = tid + i * 256;      // 0..1023
            int t2 = chunk >> 9;            // 0=Kh 1=Vh
            int c2 = chunk & 511;
            int row = c2 >> 3, seg = c2 & 7;
            size_t coloff = (t2 == 0) ? (size_t)(C_ + h * HD_) : (size_t)(2 * C_ + h * HD_);
            cp_async16(sbase + t2 * AT_KV_T + (uint32_t)(row * AT_LD + seg * 8) * 2,
                       qkvh + (size_t)(b * T_ + k0 + row) * C3_ + coloff + seg * 8);
        }
    };
    load_kv(0, 0);
    cp_commit();
    load_kv(1, 1);
    cp_commit();

    const int lrow = lane & 15;
    const int lcol = (lane >> 4) << 3;
    const int gid = lane >> 2;
    const int tig = lane & 3;

    // Wait: Q + kv0 complete (kv1 may be pending)
    cp_wait<1>();
    __syncthreads();

    // --- Q fragments (persistent) ---
    uint32_t qh[4][4], ql[4][4];
#pragma unroll
    for (int kt = 0; kt < 4; kt++) {
        uint32_t off = (uint32_t)((wid * 16 + lrow) * AT_LD + kt * 16 + lcol) * 2;
        ldm_x4(qh[kt][0], qh[kt][1], qh[kt][2], qh[kt][3], sQh + off);
        ldm_x4(ql[kt][0], ql[kt][1], ql[kt][2], ql[kt][3], sQl + off);
    }

    float o[8][4];
#pragma unroll
    for (int i = 0; i < 8; i++)
#pragma unroll
        for (int j = 0; j < 4; j++) o[i][j] = 0.f;
    float m0r = -1e30f, m1r = -1e30f, l0r = 0.f, l1r = 0.f;

    for (int it = 0; it < niters; it++) {
        if (it > 0) {
            cp_wait<1>();        // kv(it) complete
            __syncthreads();
        }

        const uint32_t s_ = stg0 + (it % AT_NSTG) * AT_STG;
        const uint32_t sKh = s_, sVh = s_ + AT_KV_T;
        const int k0 = it * 64;
        const bool active = (q0 + wid * 16 + 15 >= k0);

        if (active) {
            // ---- S = Q @ K^T (2-term: Qh·K + Ql·K) ----
            float s[8][4];
#pragma unroll
            for (int i = 0; i < 8; i++)
#pragma unroll
                for (int j = 0; j < 4; j++) s[i][j] = 0.f;

#pragma unroll
            for (int kt = 0; kt < 4; kt++) {
#pragma unroll
                for (int np = 0; np < 4; np++) {
                    uint32_t boff = (uint32_t)((np * 16 + lrow) * AT_LD + kt * 16 + lcol) * 2;
                    uint32_t h0, h1, h2, h3;
                    ldm_x4(h0, h1, h2, h3, sKh + boff);
                    mma_f16(s[np * 2],     qh[kt][0], qh[kt][1], qh[kt][2], qh[kt][3], h0, h2);
                    mma_f16(s[np * 2 + 1], qh[kt][0], qh[kt][1], qh[kt][2], qh[kt][3], h1, h3);
                    mma_f16(s[np * 2],     ql[kt][0], ql[kt][1], ql[kt][2], ql[kt][3], h0, h2);
                    mma_f16(s[np * 2 + 1], ql[kt][0], ql[kt][1], ql[kt][2], ql[kt][3], h1, h3);
                }
            }

            // ---- scale + emphasis + causal mask ----
#pragma unroll
            for (int ni = 0; ni < 8; ni++)
#pragma unroll
                for (int e = 0; e < 4; e++) s[ni][e] *= 0.125f;
            if (it == 0 && tig == 0) { s[0][0] += 1.0f; s[0][2] += 1.0f; }
            const int grow0 = q0 + wid * 16 + gid;
            const int grow1 = grow0 + 8;
            if (k0 + 63 > q0 + wid * 16) {
#pragma unroll
                for (int ni = 0; ni < 8; ni++) {
                    int gc = k0 + ni * 8 + tig * 2;
                    if (gc > grow0)     s[ni][0] = -1e30f;
                    if (gc + 1 > grow0) s[ni][1] = -1e30f;
                    if (gc > grow1)     s[ni][2] = -1e30f;
                    if (gc + 1 > grow1) s[ni][3] = -1e30f;
                }
            }

            // ---- online softmax (rows grow0, grow1) ----
            float mx0 = s[0][0], mx1 = s[0][2];
#pragma unroll
            for (int ni = 0; ni < 8; ni++) {
                mx0 = fmaxf(mx0, fmaxf(s[ni][0], s[ni][1]));
                mx1 = fmaxf(mx1, fmaxf(s[ni][2], s[ni][3]));
            }
            mx0 = fmaxf(mx0, __shfl_xor_sync(0xffffffffu, mx0, 1));
            mx0 = fmaxf(mx0, __shfl_xor_sync(0xffffffffu, mx0, 2));
            mx1 = fmaxf(mx1, __shfl_xor_sync(0xffffffffu, mx1, 1));
            mx1 = fmaxf(mx1, __shfl_xor_sync(0xffffffffu, mx1, 2));
            float mn0 = fmaxf(m0r, mx0), mn1 = fmaxf(m1r, mx1);
            float a0 = __expf(m0r - mn0), a1 = __expf(m1r - mn1);
            m0r = mn0; m1r = mn1;
            float sum0 = 0.f, sum1 = 0.f;
#pragma unroll
            for (int ni = 0; ni < 8; ni++) {
                s[ni][0] = __expf(s[ni][0] - mn0);
                s[ni][1] = __expf(s[ni][1] - mn0);
                s[ni][2] = __expf(s[ni][2] - mn1);
                s[ni][3] = __expf(s[ni][3] - mn1);
                sum0 += s[ni][0] + s[ni][1];
                sum1 += s[ni][2] + s[ni][3];
            }
            sum0 += __shfl_xor_sync(0xffffffffu, sum0, 1);
            sum0 += __shfl_xor_sync(0xffffffffu, sum0, 2);
            sum1 += __shfl_xor_sync(0xffffffffu, sum1, 1);
            sum1 += __shfl_xor_sync(0xffffffffu, sum1, 2);
            l0r = l0r * a0 + sum0;
            l1r = l1r * a1 + sum1;

            // ---- rescale O ----
#pragma unroll
            for (int ni = 0; ni < 8; ni++) {
                o[ni][0] *= a0; o[ni][1] *= a0;
                o[ni][2] *= a1; o[ni][3] *= a1;
            }

            // ---- PV (2-term: (Ph+Pl)·V), V via ldmatrix.trans ----
#pragma unroll
            for (int kt = 0; kt < 4; kt++) {
                uint32_t ph[4], pl[4];
                {
                    float v0 = s[2 * kt][0], v1 = s[2 * kt][1];
                    float v2 = s[2 * kt][2], v3 = s[2 * kt][3];
                    float w0 = s[2 * kt + 1][0], w1 = s[2 * kt + 1][1];
                    float w2 = s[2 * kt + 1][2], w3 = s[2 * kt + 1][3];
                    ph[0] = pack_f16(v0, v1); ph[1] = pack_f16(v2, v3);
                    ph[2] = pack_f16(w0, w1); ph[3] = pack_f16(w2, w3);
                    pl[0] = pack_f16(f16_residual(v0), f16_residual(v1));
                    pl[1] = pack_f16(f16_residual(v2), f16_residual(v3));
                    pl[2] = pack_f16(f16_residual(w0), f16_residual(w1));
                    pl[3] = pack_f16(f16_residual(w2), f16_residual(w3));
                }
#pragma unroll
                for (int dp = 0; dp < 4; dp++) {
                    uint32_t voff = (uint32_t)((kt * 16 + lrow) * AT_LD + dp * 16 + lcol) * 2;
                    uint32_t h0, h1, h2, h3;
                    ldm_x4_t(h0, h1, h2, h3, sVh + voff);
                    mma_f16(o[dp * 2],     ph[0], ph[1], ph[2], ph[3], h0, h1);
                    mma_f16(o[dp * 2 + 1], ph[0], ph[1], ph[2], ph[3], h2, h3);
                    mma_f16(o[dp * 2],     pl[0], pl[1], pl[2], pl[3], h0, h1);
                    mma_f16(o[dp * 2 + 1], pl[0], pl[1], pl[2], pl[3], h2, h3);
                }
            }
        }

        if (it + 2 < niters) load_kv((it + 2) % AT_NSTG, it + 2);
        cp_commit();
    }

    // ---- epilogue: normalize, split hi/lo, store ----
    const float inv0 = 1.f / l0r, inv1 = 1.f / l1r;
    const int grow0 = q0 + wid * 16 + gid;
    const size_t r0o = (size_t)(b * T_ + grow0) * C_;
    const size_t r1o = (size_t)(b * T_ + grow0 + 8) * C_;
#pragma unroll
    for (int ni = 0; ni < 8; ni++) {
        int col = h * HD_ + ni * 8 + tig * 2;
        float v0 = o[ni][0] * inv0, v1 = o[ni][1] * inv0;
        float v2 = o[ni][2] * inv1, v3 = o[ni][3] * inv1;
        *(uint32_t*)(ah + r0o + col) = pack_f16(v0, v1);
        *(uint32_t*)(al + r0o + col) = pack_f16(f16_residual(v0), f16_residual(v1));
        *(uint32_t*)(ah + r1o + col) = pack_f16(v2, v3);
        *(uint32_t*)(al + r1o + col) = pack_f16(f16_residual(v2), f16_residual(v3));
    }
}

// ---------------------------------------------------------------------------
extern "C" void kernel_launch(void* const* d_in, const int* in_sizes, int n_in,
                              void* d_out, int out_size)
{
    const float* x  = (const float*)d_in[0];
    const float* Wa = (const float*)d_in[1];
    const float* Wp = (const float*)d_in[2];
    float* y = (float*)d_out;

    __half *qkvh, *qkvl, *xh, *xl, *wah, *wph, *ah, *al;
    cudaGetSymbolAddress((void**)&qkvh, g_qkvh);
    cudaGetSymbolAddress((void**)&qkvl, g_qkvl);
    cudaGetSymbolAddress((void**)&xh, g_xh);
    cudaGetSymbolAddress((void**)&xl, g_xl);
    cudaGetSymbolAddress((void**)&wah, g_wah);
    cudaGetSymbolAddress((void**)&wph, g_wph);
    cudaGetSymbolAddress((void**)&ah, g_ah);
    cudaGetSymbolAddress((void**)&al, g_al);

    cudaFuncSetAttribute(gemm_f16x2_kernel<true>,
                         cudaFuncAttributeMaxDynamicSharedMemorySize, SMEM_GEMM);
    cudaFuncSetAttribute(gemm_f16x2_kernel<false>,
                         cudaFuncAttributeMaxDynamicSharedMemorySize, SMEM_GEMM);
    cudaFuncSetAttribute(attn_mma_kernel,
                         cudaFuncAttributeMaxDynamicSharedMemorySize, SMEM_ATTN);

    // 1) splits / weight transposes
    {
        int n4 = M_ROWS * C_ / 4;
        split_kernel<<<(n4 + 255) / 256, 256>>>(x, xh, xl, n4);
        dim3 grid_a(C3_ / 32, C_ / 32);
        transpose_f16_kernel<<<grid_a, dim3(32, 8)>>>(Wa, wah, C_, C3_);
        dim3 grid_p(C_ / 32, C_ / 32);
        transpose_f16_kernel<<<grid_p, dim3(32, 8)>>>(Wp, wph, C_, C_);
    }

    // 2) qkv = x @ W_attn -> fp16 hi/lo directly
    {
        dim3 grid(C3_ / GBN, M_ROWS / GBM);
        gemm_f16x2_kernel<true><<<grid, 256, SMEM_GEMM>>>(
            xh, xl, wah, nullptr, qkvh, qkvl, M_ROWS, C3_, C_);
    }

    // 3) flash attention -> fp16 hi/lo
    {
        dim3 grid(T_ / 128, B_ * H_);
        attn_mma_kernel<<<grid, 256, SMEM_ATTN>>>(qkvh, qkvl, ah, al);
    }

    // 4) y = att @ W_proj (fp32 out)
    {
        dim3 grid(C_ / GBN, M_ROWS / GBM);
        gemm_f16x2_kernel<false><<<grid, 256, SMEM_GEMM>>>(
            ah, al, wph, y, nullptr, nullptr, M_ROWS, C_, C_);
    }
}